// round 13
// baseline (speedup 1.0000x reference)
#include <cuda_runtime.h>
#include <cuda_bf16.h>
#include <cuda_fp16.h>
#include <cstdint>
#include <stdint.h>
#include <math.h>

#define N_NODES 50000
#define F_IN    18
#define NHEADS  8
#define CDIM    64
#define HCDIM   512
#define NE      400000
#define E_TOT   (NE + N_NODES)
#define OUT_DIM 15
#define NEG_SLOPE 0.2f

// ---------------- scratch (static device globals; no runtime allocation) ----------------
__device__ __half g_h [N_NODES * HCDIM];          // post-GEMM features (fp16)
__device__ __nv_bfloat16 g_xhi[N_NODES * HCDIM];
__device__ __nv_bfloat16 g_xlo[N_NODES * HCDIM];
__device__ __nv_bfloat16 g_w2hi[HCDIM * HCDIM];
__device__ __nv_bfloat16 g_w2lo[HCDIM * HCDIM];
__device__ __nv_bfloat16 g_w3hi[HCDIM * HCDIM];
__device__ __nv_bfloat16 g_w3lo[HCDIM * HCDIM];
__device__ float g_as[N_NODES * NHEADS];
__device__ float g_ad[N_NODES * NHEADS];
__device__ int   g_src_sorted[E_TOT];
__device__ int   g_rowptr[N_NODES + 1];
__device__ int   g_cursor[N_NODES];
__device__ int   g_counts[N_NODES];
__device__ int   g_part[64];
__device__ int   g_is64;

// ---------------- PTX helpers (portable: sm_80-era features only) ----------------
__device__ __forceinline__ uint32_t smem_u32(const void* p) {
    uint32_t a;
    asm("{ .reg .u64 t; cvta.to.shared.u64 t, %1; cvt.u32.u64 %0, t; }" : "=r"(a) : "l"(p));
    return a;
}
static __device__ __forceinline__ void cp_async16(uint32_t dst, const void* src, int sz) {
    asm volatile("cp.async.cg.shared.global [%0], [%1], 16, %2;\n"
                 :: "r"(dst), "l"(src), "r"(sz) : "memory");
}
static __device__ __forceinline__ void cp_commit() {
    asm volatile("cp.async.commit_group;" ::: "memory");
}
static __device__ __forceinline__ void cp_wait0() {
    asm volatile("cp.async.wait_group 0;" ::: "memory");
}
static __device__ __forceinline__ void cp_wait1() {
    asm volatile("cp.async.wait_group 1;" ::: "memory");
}

#define LDSM_X4(r, addr) \
    asm volatile("ldmatrix.sync.aligned.m8n8.x4.shared.b16 {%0,%1,%2,%3}, [%4];" \
        : "=r"((r)[0]), "=r"((r)[1]), "=r"((r)[2]), "=r"((r)[3]) : "r"(addr))
#define LDSM_X4_TRANS(r, addr) \
    asm volatile("ldmatrix.sync.aligned.m8n8.x4.trans.shared.b16 {%0,%1,%2,%3}, [%4];" \
        : "=r"((r)[0]), "=r"((r)[1]), "=r"((r)[2]), "=r"((r)[3]) : "r"(addr))
#define MMA_BF16(c, a, b) \
    asm volatile("mma.sync.aligned.m16n8k16.row.col.f32.bf16.bf16.f32 " \
        "{%0,%1,%2,%3},{%4,%5,%6,%7},{%8,%9},{%0,%1,%2,%3};" \
        : "+f"((c)[0]), "+f"((c)[1]), "+f"((c)[2]), "+f"((c)[3]) \
        : "r"((a)[0]), "r"((a)[1]), "r"((a)[2]), "r"((a)[3]), "r"((b)[0]), "r"((b)[1]))

// ---------------- edge dtype handling ----------------
__device__ __forceinline__ int edge_at(const int* p, int idx) {
    return g_is64 ? p[2 * idx] : p[idx];
}

// ---------------- CSR build (5 kernels) ----------------
__global__ void init_detect_kernel(const int* __restrict__ p) {
    int i = blockIdx.x * blockDim.x + threadIdx.x;
    if (i < N_NODES) g_counts[i] = 1;
    if (blockIdx.x == 0) {
        __shared__ int red[256];
        int acc = 0;
        for (int k = threadIdx.x; k < 8192; k += 256) acc |= p[2 * k + 1];
        red[threadIdx.x] = acc;
        __syncthreads();
        for (int s = 128; s > 0; s >>= 1) {
            if (threadIdx.x < s) red[threadIdx.x] |= red[threadIdx.x + s];
            __syncthreads();
        }
        if (threadIdx.x == 0) g_is64 = (red[0] == 0) ? 1 : 0;
    }
}
__global__ void count_kernel(const int* __restrict__ ei) {
    int i = blockIdx.x * blockDim.x + threadIdx.x;
    if (i < NE) atomicAdd(&g_counts[edge_at(ei, NE + i)], 1);
}
__global__ void __launch_bounds__(1024) scan_block_kernel() {
    __shared__ int sm[1024];
    int i = blockIdx.x * 1024 + threadIdx.x;
    int v = (i < N_NODES) ? g_counts[i] : 0;
    sm[threadIdx.x] = v;
    __syncthreads();
    for (int off = 1; off < 1024; off <<= 1) {
        int t = (threadIdx.x >= off) ? sm[threadIdx.x - off] : 0;
        __syncthreads();
        sm[threadIdx.x] += t;
        __syncthreads();
    }
    if (i < N_NODES) g_rowptr[i] = sm[threadIdx.x] - v;
    if (threadIdx.x == 1023) g_part[blockIdx.x] = sm[1023];
}
__global__ void __launch_bounds__(1024) scan_add_kernel() {
    __shared__ int base_s;
    if (threadIdx.x == 0) {
        int run = 0;
        for (int b = 0; b < (int)blockIdx.x; b++) run += g_part[b];
        base_s = run;
    }
    __syncthreads();
    int i = blockIdx.x * 1024 + threadIdx.x;
    if (i < N_NODES) {
        int v = g_rowptr[i] + base_s;
        g_rowptr[i] = v;
        g_cursor[i] = v;
    }
    if (i == 0) g_rowptr[N_NODES] = E_TOT;
}
__global__ void fill_kernel(const int* __restrict__ ei) {
    int i = blockIdx.x * blockDim.x + threadIdx.x;
    if (i >= E_TOT) return;
    int src, dst;
    if (i < NE) { src = edge_at(ei, i); dst = edge_at(ei, NE + i); }
    else        { src = dst = i - NE; }
    int pos = atomicAdd(&g_cursor[dst], 1);
    g_src_sorted[pos] = src;
}

// ---------------- small-K GEMM (layer 1, K=18) with fused alpha epilogue ----------------
#define BM 128
#define BN 64
#define BK 16

__global__ void __launch_bounds__(256) gemm_small_kernel(const float* __restrict__ A,
                                                         const float* __restrict__ B,
                                                         const float* __restrict__ a_src,
                                                         const float* __restrict__ a_dst,
                                                         __half* __restrict__ C,
                                                         int M, int K, int Nc) {
    __shared__ float As[BK][BM + 4];
    __shared__ float Bs[BK][BN + 4];
    int tid = threadIdx.x;
    int bn0 = blockIdx.x * BN;
    int bm0 = blockIdx.y * BM;
    int tr = tid >> 4;
    int tc = tid & 15;
    int a_row = tid >> 1;
    int a_cb  = (tid & 1) * 8;
    int b_row = tid >> 4;
    int b_col = (tid & 15) * 4;

    float acc[8][4];
#pragma unroll
    for (int i = 0; i < 8; i++)
#pragma unroll
        for (int j = 0; j < 4; j++) acc[i][j] = 0.f;

    for (int k0 = 0; k0 < K; k0 += BK) {
        int gm = bm0 + a_row;
#pragma unroll
        for (int i = 0; i < 8; i++) {
            int gk = k0 + a_cb + i;
            As[a_cb + i][a_row] = (gm < M && gk < K) ? A[(long long)gm * K + gk] : 0.f;
        }
        {
            int gk = k0 + b_row;
            float4 bv = make_float4(0.f, 0.f, 0.f, 0.f);
            if (gk < K) bv = *(const float4*)&B[(long long)gk * Nc + bn0 + b_col];
            *(float4*)&Bs[b_row][b_col] = bv;
        }
        __syncthreads();
#pragma unroll
        for (int kk = 0; kk < BK; kk++) {
            float a[8], b[4];
#pragma unroll
            for (int i = 0; i < 8; i++) a[i] = As[kk][tr * 8 + i];
#pragma unroll
            for (int j = 0; j < 4; j++) b[j] = Bs[kk][tc * 4 + j];
#pragma unroll
            for (int i = 0; i < 8; i++)
#pragma unroll
                for (int j = 0; j < 4; j++) acc[i][j] += a[i] * b[j];
        }
        __syncthreads();
    }
#pragma unroll
    for (int i = 0; i < 8; i++) {
        int gm = bm0 + tr * 8 + i;
        if (gm < M) {
            __half2 h01 = __floats2half2_rn(acc[i][0], acc[i][1]);
            __half2 h23 = __floats2half2_rn(acc[i][2], acc[i][3]);
            uint2 u;
            u.x = *(uint32_t*)&h01;
            u.y = *(uint32_t*)&h23;
            *(uint2*)&C[(size_t)gm * Nc + bn0 + tc * 4] = u;
        }
    }

    // fused alpha for this head
    {
        int hh = blockIdx.x;
        float pas[8], pad_[8];
#pragma unroll
        for (int i = 0; i < 8; i++) { pas[i] = 0.f; pad_[i] = 0.f; }
#pragma unroll
        for (int j = 0; j < 4; j++) {
            float sj = __ldg(&a_src[hh * CDIM + tc * 4 + j]);
            float dj = __ldg(&a_dst[hh * CDIM + tc * 4 + j]);
#pragma unroll
            for (int i = 0; i < 8; i++) {
                pas[i]  = fmaf(acc[i][j], sj, pas[i]);
                pad_[i] = fmaf(acc[i][j], dj, pad_[i]);
            }
        }
#pragma unroll
        for (int off = 1; off < 16; off <<= 1) {
#pragma unroll
            for (int i = 0; i < 8; i++) {
                pas[i]  += __shfl_xor_sync(0xffffffffu, pas[i], off);
                pad_[i] += __shfl_xor_sync(0xffffffffu, pad_[i], off);
            }
        }
        if (tc == 0) {
#pragma unroll
            for (int i = 0; i < 8; i++) {
                int gm = bm0 + tr * 8 + i;
                if (gm < M) {
                    g_as[gm * NHEADS + hh] = pas[i];
                    g_ad[gm * NHEADS + hh] = pad_[i];
                }
            }
        }
    }
}

// ---------------- W bf16 split (both W2 and W3 in one launch) ----------------
__global__ void __launch_bounds__(256) wsplit2_kernel(const float* __restrict__ W2,
                                                      const float* __restrict__ W3,
                                                      __nv_bfloat16* __restrict__ w2hi,
                                                      __nv_bfloat16* __restrict__ w2lo,
                                                      __nv_bfloat16* __restrict__ w3hi,
                                                      __nv_bfloat16* __restrict__ w3lo) {
    int i = blockIdx.x * blockDim.x + threadIdx.x;
    const int NW = HCDIM * HCDIM;
    if (i < NW) {
        float v = W2[i];
        __nv_bfloat16 hi = __float2bfloat16_rn(v);
        w2hi[i] = hi;
        w2lo[i] = __float2bfloat16_rn(v - __bfloat162float(hi));
    } else if (i < 2 * NW) {
        int k = i - NW;
        float v = W3[k];
        __nv_bfloat16 hi = __float2bfloat16_rn(v);
        w3hi[k] = hi;
        w3lo[k] = __float2bfloat16_rn(v - __bfloat162float(hi));
    }
}

// ---------------- mma.sync bf16-split GEMM + fused alpha epilogue ----------------
#define KTILES  (HCDIM / 32)      // 16
#define APITCH  80
#define BPITCH  272
#define A_TB    (128 * APITCH)
#define B_TB    (32 * BPITCH)
#define BUF_B   (2 * A_TB + 2 * B_TB)
#define GSMEM   (2 * BUF_B)

__global__ void __launch_bounds__(256, 2)
mma_gemm_kernel(const __nv_bfloat16* __restrict__ Ahi,
                const __nv_bfloat16* __restrict__ Alo,
                const __nv_bfloat16* __restrict__ Whi,
                const __nv_bfloat16* __restrict__ Wlo,
                const float* __restrict__ a_src,
                const float* __restrict__ a_dst,
                __half* __restrict__ C, int M) {
    extern __shared__ char smem[];
    uint32_t sb = smem_u32(smem);
    int tid = threadIdx.x, lane = tid & 31, wid = tid >> 5;
    int wm = wid & 3, wn = wid >> 2;
    int bm0 = blockIdx.y * 128, bn0 = blockIdx.x * 128;

    float acc[2][8][4];
#pragma unroll
    for (int im = 0; im < 2; im++)
#pragma unroll
        for (int in_ = 0; in_ < 8; in_++)
#pragma unroll
            for (int q = 0; q < 4; q++) acc[im][in_][q] = 0.f;

    auto load_tile = [&](int kt, int b) {
        uint32_t base = sb + (uint32_t)b * BUF_B;
#pragma unroll
        for (int m = 0; m < 2; m++) {
            const __nv_bfloat16* srcm = m ? Alo : Ahi;
            uint32_t tb = base + (uint32_t)m * A_TB;
#pragma unroll
            for (int q = 0; q < 2; q++) {
                int idx = q * 256 + tid;
                int r = idx >> 2, ch = idx & 3;
                int gr = bm0 + r;
                int sz = 16;
                if (gr >= M) { gr = 0; sz = 0; }
                cp_async16(tb + (uint32_t)(r * APITCH + ch * 16),
                           srcm + (size_t)gr * HCDIM + kt * 32 + ch * 8, sz);
            }
        }
#pragma unroll
        for (int m = 0; m < 2; m++) {
            const __nv_bfloat16* srcm = m ? Wlo : Whi;
            uint32_t tb = base + 2 * A_TB + (uint32_t)m * B_TB;
#pragma unroll
            for (int q = 0; q < 2; q++) {
                int idx = q * 256 + tid;
                int r = idx >> 4, ch = idx & 15;
                cp_async16(tb + (uint32_t)(r * BPITCH + ch * 16),
                           srcm + (size_t)(kt * 32 + r) * HCDIM + bn0 + ch * 8, 16);
            }
        }
        cp_commit();
    };

    load_tile(0, 0);

    for (int t = 0; t < KTILES; t++) {
        int b = t & 1;
        if (t + 1 < KTILES) { load_tile(t + 1, b ^ 1); cp_wait1(); }
        else cp_wait0();
        __syncthreads();

        uint32_t abase = sb + (uint32_t)b * BUF_B;
        uint32_t bbase = abase + 2 * A_TB;
#pragma unroll
        for (int ks = 0; ks < 2; ks++) {
            uint32_t ah[2][4], al[2][4];
#pragma unroll
            for (int im = 0; im < 2; im++) {
                uint32_t ra = abase
                    + (uint32_t)((wm * 32 + im * 16 + (lane & 15)) * APITCH
                                 + (ks * 16 + (lane >> 4) * 8) * 2);
                LDSM_X4(ah[im], ra);
                LDSM_X4(al[im], ra + A_TB);
            }
            int g = lane >> 3;
#pragma unroll
            for (int in2 = 0; in2 < 4; in2++) {
                uint32_t rb = bbase
                    + (uint32_t)((ks * 16 + (lane & 7) + (g & 1) * 8) * BPITCH
                                 + (wn * 64 + in2 * 16 + (g >> 1) * 8) * 2);
                uint32_t bh[4], bl[4];
                LDSM_X4_TRANS(bh, rb);
                LDSM_X4_TRANS(bl, rb + B_TB);
#pragma unroll
                for (int im = 0; im < 2; im++) {
                    MMA_BF16(acc[im][in2 * 2],     ah[im], (bh + 0));
                    MMA_BF16(acc[im][in2 * 2],     ah[im], (bl + 0));
                    MMA_BF16(acc[im][in2 * 2],     al[im], (bh + 0));
                    MMA_BF16(acc[im][in2 * 2 + 1], ah[im], (bh + 2));
                    MMA_BF16(acc[im][in2 * 2 + 1], ah[im], (bl + 2));
                    MMA_BF16(acc[im][in2 * 2 + 1], al[im], (bh + 2));
                }
            }
        }
        __syncthreads();
    }

    // ---- C store (fp16) ----
#pragma unroll
    for (int im = 0; im < 2; im++) {
        int r0 = bm0 + wm * 32 + im * 16 + (lane >> 2);
#pragma unroll
        for (int in_ = 0; in_ < 8; in_++) {
            int col = bn0 + wn * 64 + in_ * 8 + (lane & 3) * 2;
            if (r0 < M) {
                __half2 hp = __floats2half2_rn(acc[im][in_][0], acc[im][in_][1]);
                *(uint32_t*)&C[(size_t)r0 * HCDIM + col] = *(uint32_t*)&hp;
            }
            if (r0 + 8 < M) {
                __half2 hp = __floats2half2_rn(acc[im][in_][2], acc[im][in_][3]);
                *(uint32_t*)&C[(size_t)(r0 + 8) * HCDIM + col] = *(uint32_t*)&hp;
            }
        }
    }

    // ---- fused alpha: warp's 64 cols = one head ----
    {
        int hh = (bn0 >> 6) + wn;
        float pas[4] = {0.f, 0.f, 0.f, 0.f};
        float pad_[4] = {0.f, 0.f, 0.f, 0.f};
#pragma unroll
        for (int in_ = 0; in_ < 8; in_++) {
            int c0 = in_ * 8 + (lane & 3) * 2;
            float s0 = __ldg(&a_src[hh * CDIM + c0]);
            float s1 = __ldg(&a_src[hh * CDIM + c0 + 1]);
            float d0 = __ldg(&a_dst[hh * CDIM + c0]);
            float d1 = __ldg(&a_dst[hh * CDIM + c0 + 1]);
#pragma unroll
            for (int im = 0; im < 2; im++) {
                pas[im * 2]     += acc[im][in_][0] * s0 + acc[im][in_][1] * s1;
                pas[im * 2 + 1] += acc[im][in_][2] * s0 + acc[im][in_][3] * s1;
                pad_[im * 2]     += acc[im][in_][0] * d0 + acc[im][in_][1] * d1;
                pad_[im * 2 + 1] += acc[im][in_][2] * d0 + acc[im][in_][3] * d1;
            }
        }
#pragma unroll
        for (int k = 0; k < 4; k++) {
            pas[k]  += __shfl_xor_sync(0xffffffffu, pas[k], 1);
            pas[k]  += __shfl_xor_sync(0xffffffffu, pas[k], 2);
            pad_[k] += __shfl_xor_sync(0xffffffffu, pad_[k], 1);
            pad_[k] += __shfl_xor_sync(0xffffffffu, pad_[k], 2);
        }
        if ((lane & 3) == 0) {
#pragma unroll
            for (int im = 0; im < 2; im++) {
                int r0 = bm0 + wm * 32 + im * 16 + (lane >> 2);
                if (r0 < M) {
                    g_as[r0 * NHEADS + hh] = pas[im * 2];
                    g_ad[r0 * NHEADS + hh] = pad_[im * 2];
                }
                if (r0 + 8 < M) {
                    g_as[(r0 + 8) * NHEADS + hh] = pas[im * 2 + 1];
                    g_ad[(r0 + 8) * NHEADS + hh] = pad_[im * 2 + 1];
                }
            }
        }
    }
}

// ---------------- aggregation with FUSED segment softmax ----------------
// Block = one dst node, 128 threads = 8 head-groups x 16 lanes (channels).
// Prepass: each head-group computes its softmax constant C from strided edges.
// Main loop: alpha computed inline; g_as load is lane-uniform per group (L1 broadcast).
__device__ __forceinline__ uint32_t pack_bf2(float a, float b) {
    __nv_bfloat162 t;
    t.x = __float2bfloat16_rn(a);
    t.y = __float2bfloat16_rn(b);
    return *(uint32_t*)&t;
}

__device__ __forceinline__ float leaky(float e) {
    return (e > 0.f) ? e : NEG_SLOPE * e;
}

__global__ void __launch_bounds__(128) aggregate_kernel(const __half* __restrict__ hin,
                                                        const float* __restrict__ bias,
                                                        __nv_bfloat16* __restrict__ xhi,
                                                        __nv_bfloat16* __restrict__ xlo,
                                                        const float* __restrict__ Wout,
                                                        const float* __restrict__ bout,
                                                        float* __restrict__ outp,
                                                        int mode) {
    __shared__ float4 sm4[HCDIM / 4];
    __shared__ float x3row[CDIM];
    int n = blockIdx.x;
    int tid = threadIdx.x;
    int head = tid >> 4;
    int lg = tid & 15;                         // lane within head group
    int row = g_rowptr[n], end = g_rowptr[n + 1];
    float ad = __ldg(&g_ad[n * NHEADS + head]);   // uniform within group

    // ---- softmax prepass: online (m,s) over strided edges, 16-lane merge ----
    float m = -1e30f, s = 0.f;
    for (int j = row + lg; j < end; j += 16) {
        int src = __ldg(&g_src_sorted[j]);
        float e = leaky(__ldg(&g_as[src * NHEADS + head]) + ad);
        float nm = fmaxf(m, e);
        s = s * __expf(m - nm) + __expf(e - nm);
        m = nm;
    }
#pragma unroll
    for (int off = 1; off < 16; off <<= 1) {
        float mo = __shfl_xor_sync(0xffffffffu, m, off);
        float so = __shfl_xor_sync(0xffffffffu, s, off);
        float nm = fmaxf(m, mo);
        s = s * __expf(m - nm) + so * __expf(mo - nm);
        m = nm;
    }
    float Cc = m + __logf(s + 1e-16f);

    // ---- main aggregation: alpha inline ----
    const uint2* h2 = (const uint2*)hin;
    float4 acc = make_float4(0.f, 0.f, 0.f, 0.f);
    int j = row;
    for (; j + 3 < end; j += 4) {
        int s0 = __ldg(&g_src_sorted[j]);
        int s1 = __ldg(&g_src_sorted[j + 1]);
        int s2 = __ldg(&g_src_sorted[j + 2]);
        int s3 = __ldg(&g_src_sorted[j + 3]);
        float a0 = __expf(leaky(__ldg(&g_as[s0 * NHEADS + head]) + ad) - Cc);
        float a1 = __expf(leaky(__ldg(&g_as[s1 * NHEADS + head]) + ad) - Cc);
        float a2 = __expf(leaky(__ldg(&g_as[s2 * NHEADS + head]) + ad) - Cc);
        float a3 = __expf(leaky(__ldg(&g_as[s3 * NHEADS + head]) + ad) - Cc);
        uint2 u0 = __ldg(&h2[(size_t)s0 * (HCDIM / 4) + tid]);
        uint2 u1 = __ldg(&h2[(size_t)s1 * (HCDIM / 4) + tid]);
        uint2 u2 = __ldg(&h2[(size_t)s2 * (HCDIM / 4) + tid]);
        uint2 u3 = __ldg(&h2[(size_t)s3 * (HCDIM / 4) + tid]);
        float2 f0a = __half22float2(*(__half2*)&u0.x), f0b = __half22float2(*(__half2*)&u0.y);
        float2 f1a = __half22float2(*(__half2*)&u1.x), f1b = __half22float2(*(__half2*)&u1.y);
        float2 f2a = __half22float2(*(__half2*)&u2.x), f2b = __half22float2(*(__half2*)&u2.y);
        float2 f3a = __half22float2(*(__half2*)&u3.x), f3b = __half22float2(*(__half2*)&u3.y);
        acc.x = fmaf(a0, f0a.x, fmaf(a1, f1a.x, fmaf(a2, f2a.x, fmaf(a3, f3a.x, acc.x))));
        acc.y = fmaf(a0, f0a.y, fmaf(a1, f1a.y, fmaf(a2, f2a.y, fmaf(a3, f3a.y, acc.y))));
        acc.z = fmaf(a0, f0b.x, fmaf(a1, f1b.x, fmaf(a2, f2b.x, fmaf(a3, f3b.x, acc.z))));
        acc.w = fmaf(a0, f0b.y, fmaf(a1, f1b.y, fmaf(a2, f2b.y, fmaf(a3, f3b.y, acc.w))));
    }
    for (; j < end; j++) {
        int s0 = __ldg(&g_src_sorted[j]);
        float a0 = __expf(leaky(__ldg(&g_as[s0 * NHEADS + head]) + ad) - Cc);
        uint2 u0 = __ldg(&h2[(size_t)s0 * (HCDIM / 4) + tid]);
        float2 f0a = __half22float2(*(__half2*)&u0.x);
        float2 f0b = __half22float2(*(__half2*)&u0.y);
        acc.x = fmaf(a0, f0a.x, acc.x);
        acc.y = fmaf(a0, f0a.y, acc.y);
        acc.z = fmaf(a0, f0b.x, acc.z);
        acc.w = fmaf(a0, f0b.y, acc.w);
    }
    if (mode == 0) {
        float4 b4 = ((const float4*)bias)[tid];
        float vx = acc.x + b4.x; vx = (vx > 0.f) ? vx : expm1f(vx);
        float vy = acc.y + b4.y; vy = (vy > 0.f) ? vy : expm1f(vy);
        float vz = acc.z + b4.z; vz = (vz > 0.f) ? vz : expm1f(vz);
        float vw = acc.w + b4.w; vw = (vw > 0.f) ? vw : expm1f(vw);
        __nv_bfloat16 hx = __float2bfloat16_rn(vx), hy = __float2bfloat16_rn(vy);
        __nv_bfloat16 hz = __float2bfloat16_rn(vz), hw = __float2bfloat16_rn(vw);
        float lx = vx - __bfloat162float(hx), ly = vy - __bfloat162float(hy);
        float lz = vz - __bfloat162float(hz), lw = vw - __bfloat162float(hw);
        size_t base = ((size_t)n * HCDIM + tid * 4) >> 1;
        uint32_t* hip = (uint32_t*)xhi;
        uint32_t* lop = (uint32_t*)xlo;
        __nv_bfloat162 h01; h01.x = hx; h01.y = hy;
        __nv_bfloat162 h23; h23.x = hz; h23.y = hw;
        hip[base]     = *(uint32_t*)&h01;
        hip[base + 1] = *(uint32_t*)&h23;
        lop[base]     = pack_bf2(lx, ly);
        lop[base + 1] = pack_bf2(lz, lw);
    } else {
        sm4[tid] = acc;
        __syncthreads();
        if (tid < 16) {
            float4 sacc = make_float4(0.f, 0.f, 0.f, 0.f);
#pragma unroll
            for (int hh = 0; hh < NHEADS; hh++) {
                float4 f = sm4[hh * 16 + tid];
                sacc.x += f.x; sacc.y += f.y; sacc.z += f.z; sacc.w += f.w;
            }
            float4 b4 = ((const float4*)bias)[tid];
            x3row[tid * 4 + 0] = sacc.x * (1.0f / NHEADS) + b4.x;
            x3row[tid * 4 + 1] = sacc.y * (1.0f / NHEADS) + b4.y;
            x3row[tid * 4 + 2] = sacc.z * (1.0f / NHEADS) + b4.z;
            x3row[tid * 4 + 3] = sacc.w * (1.0f / NHEADS) + b4.w;
        }
        __syncthreads();
        int o = tid >> 3, c8 = tid & 7;
        float accp = 0.f;
        if (o < OUT_DIM) {
#pragma unroll
            for (int c = 0; c < 8; c++) {
                int cc = c8 * 8 + c;
                accp = fmaf(x3row[cc], __ldg(&Wout[cc * OUT_DIM + o]), accp);
            }
        }
        accp += __shfl_xor_sync(0xffffffffu, accp, 1);
        accp += __shfl_xor_sync(0xffffffffu, accp, 2);
        accp += __shfl_xor_sync(0xffffffffu, accp, 4);
        if (c8 == 0 && o < OUT_DIM)
            outp[(size_t)n * OUT_DIM + o] = accp + __ldg(&bout[o]);
    }
}

// ---------------- launch ----------------
extern "C" void kernel_launch(void* const* d_in, const int* in_sizes, int n_in,
                              void* d_out, int out_size) {
    const float* x    = (const float*)d_in[0];
    const int*   ei   = (const int*)d_in[1];
    const float* W1   = (const float*)d_in[2];
    const float* a1s  = (const float*)d_in[3];
    const float* a1d  = (const float*)d_in[4];
    const float* b1   = (const float*)d_in[5];
    const float* W2   = (const float*)d_in[6];
    const float* a2s  = (const float*)d_in[7];
    const float* a2d  = (const float*)d_in[8];
    const float* b2   = (const float*)d_in[9];
    const float* W3   = (const float*)d_in[10];
    const float* a3s  = (const float*)d_in[11];
    const float* a3d  = (const float*)d_in[12];
    const float* b3   = (const float*)d_in[13];
    const float* Wout = (const float*)d_in[14];
    const float* bout = (const float*)d_in[15];
    float* out = (float*)d_out;

    __half *p_h;
    __nv_bfloat16 *p_xhi, *p_xlo, *p_w2hi, *p_w2lo, *p_w3hi, *p_w3lo;
    cudaGetSymbolAddress((void**)&p_h,    g_h);
    cudaGetSymbolAddress((void**)&p_xhi,  g_xhi);
    cudaGetSymbolAddress((void**)&p_xlo,  g_xlo);
    cudaGetSymbolAddress((void**)&p_w2hi, g_w2hi);
    cudaGetSymbolAddress((void**)&p_w2lo, g_w2lo);
    cudaGetSymbolAddress((void**)&p_w3hi, g_w3hi);
    cudaGetSymbolAddress((void**)&p_w3lo, g_w3lo);

    cudaFuncSetAttribute(mma_gemm_kernel, cudaFuncAttributeMaxDynamicSharedMemorySize, GSMEM);

    const int scan_blocks = (N_NODES + 1023) / 1024;

    init_detect_kernel<<<(N_NODES + 255) / 256, 256>>>(ei);
    count_kernel<<<(NE + 255) / 256, 256>>>(ei);
    scan_block_kernel<<<scan_blocks, 1024>>>();
    scan_add_kernel<<<scan_blocks, 1024>>>();
    fill_kernel<<<(E_TOT + 255) / 256, 256>>>(ei);

    int wsplit_blocks = (2 * HCDIM * HCDIM + 255) / 256;
    wsplit2_kernel<<<wsplit_blocks, 256>>>(W2, W3, p_w2hi, p_w2lo, p_w3hi, p_w3lo);

    dim3 sgrid(HCDIM / BN, (N_NODES + BM - 1) / BM);
    dim3 mgrid(HCDIM / 128, (N_NODES + 127) / 128);

    // ---- layer 1 ----
    gemm_small_kernel<<<sgrid, 256>>>(x, W1, a1s, a1d, p_h, N_NODES, F_IN, HCDIM);
    aggregate_kernel<<<N_NODES, 128>>>(p_h, b1, p_xhi, p_xlo, nullptr, nullptr, nullptr, 0);

    // ---- layer 2 ----
    mma_gemm_kernel<<<mgrid, 256, GSMEM>>>(p_xhi, p_xlo, p_w2hi, p_w2lo, a2s, a2d, p_h, N_NODES);
    aggregate_kernel<<<N_NODES, 128>>>(p_h, b2, p_xhi, p_xlo, nullptr, nullptr, nullptr, 0);

    // ---- layer 3 (aggregate + softmax + mean + bias + projection fused) ----
    mma_gemm_kernel<<<mgrid, 256, GSMEM>>>(p_xhi, p_xlo, p_w3hi, p_w3lo, a3s, a3d, p_h, N_NODES);
    aggregate_kernel<<<N_NODES, 128>>>(p_h, b3, nullptr, nullptr, Wout, bout, out, 1);
}

// round 14
// speedup vs baseline: 1.0571x; 1.0571x over previous
#include <cuda_runtime.h>
#include <cuda_bf16.h>
#include <cuda_fp16.h>
#include <cstdint>
#include <stdint.h>
#include <math.h>

#define N_NODES 50000
#define F_IN    18
#define NHEADS  8
#define CDIM    64
#define HCDIM   512
#define NE      400000
#define E_TOT   (NE + N_NODES)
#define OUT_DIM 15
#define NEG_SLOPE 0.2f

// ---------------- scratch (static device globals; no runtime allocation) ----------------
__device__ __half g_h [N_NODES * HCDIM];          // post-GEMM features (fp16)
__device__ __nv_bfloat16 g_xhi[N_NODES * HCDIM];
__device__ __nv_bfloat16 g_xlo[N_NODES * HCDIM];
__device__ __nv_bfloat16 g_w2hi[HCDIM * HCDIM];
__device__ __nv_bfloat16 g_w2lo[HCDIM * HCDIM];
__device__ __nv_bfloat16 g_w3hi[HCDIM * HCDIM];
__device__ __nv_bfloat16 g_w3lo[HCDIM * HCDIM];
__device__ float g_as[N_NODES * NHEADS];
__device__ float g_ad[N_NODES * NHEADS];
__device__ float g_C [N_NODES * NHEADS];          // softmax constant: m + log(s+eps)
__device__ float g_alpha[(size_t)E_TOT * NHEADS]; // raw e (LeakyReLU'd logits)
__device__ int   g_src_sorted[E_TOT];
__device__ int   g_rowptr[N_NODES + 1];
__device__ int   g_cursor[N_NODES];
__device__ int   g_counts[N_NODES];
__device__ int   g_part[64];
__device__ int   g_is64;

// ---------------- PTX helpers (portable: sm_80-era features only) ----------------
__device__ __forceinline__ uint32_t smem_u32(const void* p) {
    uint32_t a;
    asm("{ .reg .u64 t; cvta.to.shared.u64 t, %1; cvt.u32.u64 %0, t; }" : "=r"(a) : "l"(p));
    return a;
}
static __device__ __forceinline__ void cp_async16(uint32_t dst, const void* src, int sz) {
    asm volatile("cp.async.cg.shared.global [%0], [%1], 16, %2;\n"
                 :: "r"(dst), "l"(src), "r"(sz) : "memory");
}
static __device__ __forceinline__ void cp_commit() {
    asm volatile("cp.async.commit_group;" ::: "memory");
}
static __device__ __forceinline__ void cp_wait0() {
    asm volatile("cp.async.wait_group 0;" ::: "memory");
}
static __device__ __forceinline__ void cp_wait1() {
    asm volatile("cp.async.wait_group 1;" ::: "memory");
}

#define LDSM_X4(r, addr) \
    asm volatile("ldmatrix.sync.aligned.m8n8.x4.shared.b16 {%0,%1,%2,%3}, [%4];" \
        : "=r"((r)[0]), "=r"((r)[1]), "=r"((r)[2]), "=r"((r)[3]) : "r"(addr))
#define LDSM_X4_TRANS(r, addr) \
    asm volatile("ldmatrix.sync.aligned.m8n8.x4.trans.shared.b16 {%0,%1,%2,%3}, [%4];" \
        : "=r"((r)[0]), "=r"((r)[1]), "=r"((r)[2]), "=r"((r)[3]) : "r"(addr))
#define MMA_BF16(c, a, b) \
    asm volatile("mma.sync.aligned.m16n8k16.row.col.f32.bf16.bf16.f32 " \
        "{%0,%1,%2,%3},{%4,%5,%6,%7},{%8,%9},{%0,%1,%2,%3};" \
        : "+f"((c)[0]), "+f"((c)[1]), "+f"((c)[2]), "+f"((c)[3]) \
        : "r"((a)[0]), "r"((a)[1]), "r"((a)[2]), "r"((a)[3]), "r"((b)[0]), "r"((b)[1]))

// ---------------- edge dtype handling ----------------
__device__ __forceinline__ int edge_at(const int* p, int idx) {
    return g_is64 ? p[2 * idx] : p[idx];
}

// ---------------- CSR build (5 kernels) ----------------
__global__ void init_detect_kernel(const int* __restrict__ p) {
    int i = blockIdx.x * blockDim.x + threadIdx.x;
    if (i < N_NODES) g_counts[i] = 1;
    if (blockIdx.x == 0) {
        __shared__ int red[256];
        int acc = 0;
        for (int k = threadIdx.x; k < 8192; k += 256) acc |= p[2 * k + 1];
        red[threadIdx.x] = acc;
        __syncthreads();
        for (int s = 128; s > 0; s >>= 1) {
            if (threadIdx.x < s) red[threadIdx.x] |= red[threadIdx.x + s];
            __syncthreads();
        }
        if (threadIdx.x == 0) g_is64 = (red[0] == 0) ? 1 : 0;
    }
}
__global__ void count_kernel(const int* __restrict__ ei) {
    int i = blockIdx.x * blockDim.x + threadIdx.x;
    if (i < NE) atomicAdd(&g_counts[edge_at(ei, NE + i)], 1);
}
__global__ void __launch_bounds__(1024) scan_block_kernel() {
    __shared__ int sm[1024];
    int i = blockIdx.x * 1024 + threadIdx.x;
    int v = (i < N_NODES) ? g_counts[i] : 0;
    sm[threadIdx.x] = v;
    __syncthreads();
    for (int off = 1; off < 1024; off <<= 1) {
        int t = (threadIdx.x >= off) ? sm[threadIdx.x - off] : 0;
        __syncthreads();
        sm[threadIdx.x] += t;
        __syncthreads();
    }
    if (i < N_NODES) g_rowptr[i] = sm[threadIdx.x] - v;   // local exclusive
    if (threadIdx.x == 1023) g_part[blockIdx.x] = sm[1023];  // raw block totals
}
__global__ void __launch_bounds__(1024) scan_add_kernel() {
    __shared__ int base_s;
    if (threadIdx.x == 0) {
        int run = 0;
        for (int b = 0; b < (int)blockIdx.x; b++) run += g_part[b];
        base_s = run;
    }
    __syncthreads();
    int i = blockIdx.x * 1024 + threadIdx.x;
    if (i < N_NODES) {
        int v = g_rowptr[i] + base_s;
        g_rowptr[i] = v;
        g_cursor[i] = v;
    }
    if (i == 0) g_rowptr[N_NODES] = E_TOT;
}
__global__ void fill_kernel(const int* __restrict__ ei) {
    int i = blockIdx.x * blockDim.x + threadIdx.x;
    if (i >= E_TOT) return;
    int src, dst;
    if (i < NE) { src = edge_at(ei, i); dst = edge_at(ei, NE + i); }
    else        { src = dst = i - NE; }
    int pos = atomicAdd(&g_cursor[dst], 1);
    g_src_sorted[pos] = src;
}

// ---------------- small-K GEMM (layer 1, K=18) with fused alpha epilogue ----------------
#define BM 128
#define BN 64
#define BK 16

__global__ void __launch_bounds__(256) gemm_small_kernel(const float* __restrict__ A,
                                                         const float* __restrict__ B,
                                                         const float* __restrict__ a_src,
                                                         const float* __restrict__ a_dst,
                                                         __half* __restrict__ C,
                                                         int M, int K, int Nc) {
    __shared__ float As[BK][BM + 4];
    __shared__ float Bs[BK][BN + 4];
    int tid = threadIdx.x;
    int bn0 = blockIdx.x * BN;
    int bm0 = blockIdx.y * BM;
    int tr = tid >> 4;
    int tc = tid & 15;
    int a_row = tid >> 1;
    int a_cb  = (tid & 1) * 8;
    int b_row = tid >> 4;
    int b_col = (tid & 15) * 4;

    float acc[8][4];
#pragma unroll
    for (int i = 0; i < 8; i++)
#pragma unroll
        for (int j = 0; j < 4; j++) acc[i][j] = 0.f;

    for (int k0 = 0; k0 < K; k0 += BK) {
        int gm = bm0 + a_row;
#pragma unroll
        for (int i = 0; i < 8; i++) {
            int gk = k0 + a_cb + i;
            As[a_cb + i][a_row] = (gm < M && gk < K) ? A[(long long)gm * K + gk] : 0.f;
        }
        {
            int gk = k0 + b_row;
            float4 bv = make_float4(0.f, 0.f, 0.f, 0.f);
            if (gk < K) bv = *(const float4*)&B[(long long)gk * Nc + bn0 + b_col];
            *(float4*)&Bs[b_row][b_col] = bv;
        }
        __syncthreads();
#pragma unroll
        for (int kk = 0; kk < BK; kk++) {
            float a[8], b[4];
#pragma unroll
            for (int i = 0; i < 8; i++) a[i] = As[kk][tr * 8 + i];
#pragma unroll
            for (int j = 0; j < 4; j++) b[j] = Bs[kk][tc * 4 + j];
#pragma unroll
            for (int i = 0; i < 8; i++)
#pragma unroll
                for (int j = 0; j < 4; j++) acc[i][j] += a[i] * b[j];
        }
        __syncthreads();
    }
#pragma unroll
    for (int i = 0; i < 8; i++) {
        int gm = bm0 + tr * 8 + i;
        if (gm < M) {
            __half2 h01 = __floats2half2_rn(acc[i][0], acc[i][1]);
            __half2 h23 = __floats2half2_rn(acc[i][2], acc[i][3]);
            uint2 u;
            u.x = *(uint32_t*)&h01;
            u.y = *(uint32_t*)&h23;
            *(uint2*)&C[(size_t)gm * Nc + bn0 + tc * 4] = u;
        }
    }

    // fused alpha for this head
    {
        int hh = blockIdx.x;
        float pas[8], pad_[8];
#pragma unroll
        for (int i = 0; i < 8; i++) { pas[i] = 0.f; pad_[i] = 0.f; }
#pragma unroll
        for (int j = 0; j < 4; j++) {
            float sj = __ldg(&a_src[hh * CDIM + tc * 4 + j]);
            float dj = __ldg(&a_dst[hh * CDIM + tc * 4 + j]);
#pragma unroll
            for (int i = 0; i < 8; i++) {
                pas[i]  = fmaf(acc[i][j], sj, pas[i]);
                pad_[i] = fmaf(acc[i][j], dj, pad_[i]);
            }
        }
#pragma unroll
        for (int off = 1; off < 16; off <<= 1) {
#pragma unroll
            for (int i = 0; i < 8; i++) {
                pas[i]  += __shfl_xor_sync(0xffffffffu, pas[i], off);
                pad_[i] += __shfl_xor_sync(0xffffffffu, pad_[i], off);
            }
        }
        if (tc == 0) {
#pragma unroll
            for (int i = 0; i < 8; i++) {
                int gm = bm0 + tr * 8 + i;
                if (gm < M) {
                    g_as[gm * NHEADS + hh] = pas[i];
                    g_ad[gm * NHEADS + hh] = pad_[i];
                }
            }
        }
    }
}

// ---------------- W bf16 split (both W2 and W3 in one launch) ----------------
__global__ void __launch_bounds__(256) wsplit2_kernel(const float* __restrict__ W2,
                                                      const float* __restrict__ W3,
                                                      __nv_bfloat16* __restrict__ w2hi,
                                                      __nv_bfloat16* __restrict__ w2lo,
                                                      __nv_bfloat16* __restrict__ w3hi,
                                                      __nv_bfloat16* __restrict__ w3lo) {
    int i = blockIdx.x * blockDim.x + threadIdx.x;
    const int NW = HCDIM * HCDIM;
    if (i < NW) {
        float v = W2[i];
        __nv_bfloat16 hi = __float2bfloat16_rn(v);
        w2hi[i] = hi;
        w2lo[i] = __float2bfloat16_rn(v - __bfloat162float(hi));
    } else if (i < 2 * NW) {
        int k = i - NW;
        float v = W3[k];
        __nv_bfloat16 hi = __float2bfloat16_rn(v);
        w3hi[k] = hi;
        w3lo[k] = __float2bfloat16_rn(v - __bfloat162float(hi));
    }
}

// ---------------- mma.sync bf16-split GEMM + fused alpha epilogue ----------------
#define KTILES  (HCDIM / 32)      // 16
#define APITCH  80
#define BPITCH  272
#define A_TB    (128 * APITCH)
#define B_TB    (32 * BPITCH)
#define BUF_B   (2 * A_TB + 2 * B_TB)
#define GSMEM   (2 * BUF_B)

__global__ void __launch_bounds__(256, 2)
mma_gemm_kernel(const __nv_bfloat16* __restrict__ Ahi,
                const __nv_bfloat16* __restrict__ Alo,
                const __nv_bfloat16* __restrict__ Whi,
                const __nv_bfloat16* __restrict__ Wlo,
                const float* __restrict__ a_src,
                const float* __restrict__ a_dst,
                __half* __restrict__ C, int M) {
    extern __shared__ char smem[];
    uint32_t sb = smem_u32(smem);
    int tid = threadIdx.x, lane = tid & 31, wid = tid >> 5;
    int wm = wid & 3, wn = wid >> 2;
    int bm0 = blockIdx.y * 128, bn0 = blockIdx.x * 128;

    float acc[2][8][4];
#pragma unroll
    for (int im = 0; im < 2; im++)
#pragma unroll
        for (int in_ = 0; in_ < 8; in_++)
#pragma unroll
            for (int q = 0; q < 4; q++) acc[im][in_][q] = 0.f;

    auto load_tile = [&](int kt, int b) {
        uint32_t base = sb + (uint32_t)b * BUF_B;
#pragma unroll
        for (int m = 0; m < 2; m++) {
            const __nv_bfloat16* srcm = m ? Alo : Ahi;
            uint32_t tb = base + (uint32_t)m * A_TB;
#pragma unroll
            for (int q = 0; q < 2; q++) {
                int idx = q * 256 + tid;
                int r = idx >> 2, ch = idx & 3;
                int gr = bm0 + r;
                int sz = 16;
                if (gr >= M) { gr = 0; sz = 0; }
                cp_async16(tb + (uint32_t)(r * APITCH + ch * 16),
                           srcm + (size_t)gr * HCDIM + kt * 32 + ch * 8, sz);
            }
        }
#pragma unroll
        for (int m = 0; m < 2; m++) {
            const __nv_bfloat16* srcm = m ? Wlo : Whi;
            uint32_t tb = base + 2 * A_TB + (uint32_t)m * B_TB;
#pragma unroll
            for (int q = 0; q < 2; q++) {
                int idx = q * 256 + tid;
                int r = idx >> 4, ch = idx & 15;
                cp_async16(tb + (uint32_t)(r * BPITCH + ch * 16),
                           srcm + (size_t)(kt * 32 + r) * HCDIM + bn0 + ch * 8, 16);
            }
        }
        cp_commit();
    };

    load_tile(0, 0);

    for (int t = 0; t < KTILES; t++) {
        int b = t & 1;
        if (t + 1 < KTILES) { load_tile(t + 1, b ^ 1); cp_wait1(); }
        else cp_wait0();
        __syncthreads();

        uint32_t abase = sb + (uint32_t)b * BUF_B;
        uint32_t bbase = abase + 2 * A_TB;
#pragma unroll
        for (int ks = 0; ks < 2; ks++) {
            uint32_t ah[2][4], al[2][4];
#pragma unroll
            for (int im = 0; im < 2; im++) {
                uint32_t ra = abase
                    + (uint32_t)((wm * 32 + im * 16 + (lane & 15)) * APITCH
                                 + (ks * 16 + (lane >> 4) * 8) * 2);
                LDSM_X4(ah[im], ra);
                LDSM_X4(al[im], ra + A_TB);
            }
            int g = lane >> 3;
#pragma unroll
            for (int in2 = 0; in2 < 4; in2++) {
                uint32_t rb = bbase
                    + (uint32_t)((ks * 16 + (lane & 7) + (g & 1) * 8) * BPITCH
                                 + (wn * 64 + in2 * 16 + (g >> 1) * 8) * 2);
                uint32_t bh[4], bl[4];
                LDSM_X4_TRANS(bh, rb);
                LDSM_X4_TRANS(bl, rb + B_TB);
#pragma unroll
                for (int im = 0; im < 2; im++) {
                    MMA_BF16(acc[im][in2 * 2],     ah[im], (bh + 0));
                    MMA_BF16(acc[im][in2 * 2],     ah[im], (bl + 0));
                    MMA_BF16(acc[im][in2 * 2],     al[im], (bh + 0));
                    MMA_BF16(acc[im][in2 * 2 + 1], ah[im], (bh + 2));
                    MMA_BF16(acc[im][in2 * 2 + 1], ah[im], (bl + 2));
                    MMA_BF16(acc[im][in2 * 2 + 1], al[im], (bh + 2));
                }
            }
        }
        __syncthreads();
    }

    // ---- C store (fp16) ----
#pragma unroll
    for (int im = 0; im < 2; im++) {
        int r0 = bm0 + wm * 32 + im * 16 + (lane >> 2);
#pragma unroll
        for (int in_ = 0; in_ < 8; in_++) {
            int col = bn0 + wn * 64 + in_ * 8 + (lane & 3) * 2;
            if (r0 < M) {
                __half2 hp = __floats2half2_rn(acc[im][in_][0], acc[im][in_][1]);
                *(uint32_t*)&C[(size_t)r0 * HCDIM + col] = *(uint32_t*)&hp;
            }
            if (r0 + 8 < M) {
                __half2 hp = __floats2half2_rn(acc[im][in_][2], acc[im][in_][3]);
                *(uint32_t*)&C[(size_t)(r0 + 8) * HCDIM + col] = *(uint32_t*)&hp;
            }
        }
    }

    // ---- fused alpha: warp's 64 cols = one head ----
    {
        int hh = (bn0 >> 6) + wn;
        float pas[4] = {0.f, 0.f, 0.f, 0.f};
        float pad_[4] = {0.f, 0.f, 0.f, 0.f};
#pragma unroll
        for (int in_ = 0; in_ < 8; in_++) {
            int c0 = in_ * 8 + (lane & 3) * 2;
            float s0 = __ldg(&a_src[hh * CDIM + c0]);
            float s1 = __ldg(&a_src[hh * CDIM + c0 + 1]);
            float d0 = __ldg(&a_dst[hh * CDIM + c0]);
            float d1 = __ldg(&a_dst[hh * CDIM + c0 + 1]);
#pragma unroll
            for (int im = 0; im < 2; im++) {
                pas[im * 2]     += acc[im][in_][0] * s0 + acc[im][in_][1] * s1;
                pas[im * 2 + 1] += acc[im][in_][2] * s0 + acc[im][in_][3] * s1;
                pad_[im * 2]     += acc[im][in_][0] * d0 + acc[im][in_][1] * d1;
                pad_[im * 2 + 1] += acc[im][in_][2] * d0 + acc[im][in_][3] * d1;
            }
        }
#pragma unroll
        for (int k = 0; k < 4; k++) {
            pas[k]  += __shfl_xor_sync(0xffffffffu, pas[k], 1);
            pas[k]  += __shfl_xor_sync(0xffffffffu, pas[k], 2);
            pad_[k] += __shfl_xor_sync(0xffffffffu, pad_[k], 1);
            pad_[k] += __shfl_xor_sync(0xffffffffu, pad_[k], 2);
        }
        if ((lane & 3) == 0) {
#pragma unroll
            for (int im = 0; im < 2; im++) {
                int r0 = bm0 + wm * 32 + im * 16 + (lane >> 2);
                if (r0 < M) {
                    g_as[r0 * NHEADS + hh] = pas[im * 2];
                    g_ad[r0 * NHEADS + hh] = pad_[im * 2];
                }
                if (r0 + 8 < M) {
                    g_as[(r0 + 8) * NHEADS + hh] = pas[im * 2 + 1];
                    g_ad[(r0 + 8) * NHEADS + hh] = pad_[im * 2 + 1];
                }
            }
        }
    }
}

// ---------------- segment softmax: warp per node, 4 edges x 8 heads per iter ----------------
__global__ void stats_kernel() {
    int lane = threadIdx.x & 31;
    int n = (blockIdx.x * blockDim.x + threadIdx.x) >> 5;
    int hh = lane & 7, sub = lane >> 3;
    if (n >= N_NODES) return;
    int row = g_rowptr[n], end = g_rowptr[n + 1];
    float ad = g_ad[n * NHEADS + hh];
    float m = -1e30f, s = 0.f;
    for (int j = row + sub; j < end; j += 4) {
        int src = g_src_sorted[j];
        float e = g_as[src * NHEADS + hh] + ad;
        e = (e > 0.f) ? e : NEG_SLOPE * e;
        g_alpha[(size_t)j * NHEADS + hh] = e;
        float nm = fmaxf(m, e);
        s = s * __expf(m - nm) + __expf(e - nm);
        m = nm;
    }
#pragma unroll
    for (int off = 8; off <= 16; off <<= 1) {
        float mo = __shfl_xor_sync(0xffffffffu, m, off);
        float so = __shfl_xor_sync(0xffffffffu, s, off);
        float nm = fmaxf(m, mo);
        s = s * __expf(m - nm) + so * __expf(mo - nm);
        m = nm;
    }
    if (sub == 0) g_C[n * NHEADS + hh] = m + __logf(s + 1e-16f);
}

// ---------------- heavy aggregation (fp16 h, alpha inline; mode 1 fuses projection) -----
__device__ __forceinline__ uint32_t pack_bf2(float a, float b) {
    __nv_bfloat162 t;
    t.x = __float2bfloat16_rn(a);
    t.y = __float2bfloat16_rn(b);
    return *(uint32_t*)&t;
}

__global__ void __launch_bounds__(128) aggregate_kernel(const __half* __restrict__ hin,
                                                        const float* __restrict__ bias,
                                                        __nv_bfloat16* __restrict__ xhi,
                                                        __nv_bfloat16* __restrict__ xlo,
                                                        const float* __restrict__ Wout,
                                                        const float* __restrict__ bout,
                                                        float* __restrict__ outp,
                                                        int mode) {
    __shared__ float4 sm4[HCDIM / 4];
    __shared__ float x3row[CDIM];
    int n = blockIdx.x;
    int tid = threadIdx.x;
    int head = tid >> 4;
    int row = g_rowptr[n], end = g_rowptr[n + 1];
    float Cc = __ldg(&g_C[n * NHEADS + head]);
    const uint2* h2 = (const uint2*)hin;
    float4 acc = make_float4(0.f, 0.f, 0.f, 0.f);
    int j = row;
    for (; j + 3 < end; j += 4) {
        int s0 = __ldg(&g_src_sorted[j]);
        int s1 = __ldg(&g_src_sorted[j + 1]);
        int s2 = __ldg(&g_src_sorted[j + 2]);
        int s3 = __ldg(&g_src_sorted[j + 3]);
        float a0 = __expf(__ldg(&g_alpha[(size_t)j * NHEADS + head]) - Cc);
        float a1 = __expf(__ldg(&g_alpha[(size_t)(j + 1) * NHEADS + head]) - Cc);
        float a2 = __expf(__ldg(&g_alpha[(size_t)(j + 2) * NHEADS + head]) - Cc);
        float a3 = __expf(__ldg(&g_alpha[(size_t)(j + 3) * NHEADS + head]) - Cc);
        uint2 u0 = __ldg(&h2[(size_t)s0 * (HCDIM / 4) + tid]);
        uint2 u1 = __ldg(&h2[(size_t)s1 * (HCDIM / 4) + tid]);
        uint2 u2 = __ldg(&h2[(size_t)s2 * (HCDIM / 4) + tid]);
        uint2 u3 = __ldg(&h2[(size_t)s3 * (HCDIM / 4) + tid]);
        float2 f0a = __half22float2(*(__half2*)&u0.x), f0b = __half22float2(*(__half2*)&u0.y);
        float2 f1a = __half22float2(*(__half2*)&u1.x), f1b = __half22float2(*(__half2*)&u1.y);
        float2 f2a = __half22float2(*(__half2*)&u2.x), f2b = __half22float2(*(__half2*)&u2.y);
        float2 f3a = __half22float2(*(__half2*)&u3.x), f3b = __half22float2(*(__half2*)&u3.y);
        acc.x = fmaf(a0, f0a.x, fmaf(a1, f1a.x, fmaf(a2, f2a.x, fmaf(a3, f3a.x, acc.x))));
        acc.y = fmaf(a0, f0a.y, fmaf(a1, f1a.y, fmaf(a2, f2a.y, fmaf(a3, f3a.y, acc.y))));
        acc.z = fmaf(a0, f0b.x, fmaf(a1, f1b.x, fmaf(a2, f2b.x, fmaf(a3, f3b.x, acc.z))));
        acc.w = fmaf(a0, f0b.y, fmaf(a1, f1b.y, fmaf(a2, f2b.y, fmaf(a3, f3b.y, acc.w))));
    }
    for (; j < end; j++) {
        int s0 = __ldg(&g_src_sorted[j]);
        float a0 = __expf(__ldg(&g_alpha[(size_t)j * NHEADS + head]) - Cc);
        uint2 u0 = __ldg(&h2[(size_t)s0 * (HCDIM / 4) + tid]);
        float2 f0a = __half22float2(*(__half2*)&u0.x);
        float2 f0b = __half22float2(*(__half2*)&u0.y);
        acc.x = fmaf(a0, f0a.x, acc.x);
        acc.y = fmaf(a0, f0a.y, acc.y);
        acc.z = fmaf(a0, f0b.x, acc.z);
        acc.w = fmaf(a0, f0b.y, acc.w);
    }
    if (mode == 0) {
        float4 b4 = ((const float4*)bias)[tid];
        float vx = acc.x + b4.x; vx = (vx > 0.f) ? vx : expm1f(vx);
        float vy = acc.y + b4.y; vy = (vy > 0.f) ? vy : expm1f(vy);
        float vz = acc.z + b4.z; vz = (vz > 0.f) ? vz : expm1f(vz);
        float vw = acc.w + b4.w; vw = (vw > 0.f) ? vw : expm1f(vw);
        __nv_bfloat16 hx = __float2bfloat16_rn(vx), hy = __float2bfloat16_rn(vy);
        __nv_bfloat16 hz = __float2bfloat16_rn(vz), hw = __float2bfloat16_rn(vw);
        float lx = vx - __bfloat162float(hx), ly = vy - __bfloat162float(hy);
        float lz = vz - __bfloat162float(hz), lw = vw - __bfloat162float(hw);
        size_t base = ((size_t)n * HCDIM + tid * 4) >> 1;
        uint32_t* hip = (uint32_t*)xhi;
        uint32_t* lop = (uint32_t*)xlo;
        __nv_bfloat162 h01; h01.x = hx; h01.y = hy;
        __nv_bfloat162 h23; h23.x = hz; h23.y = hw;
        hip[base]     = *(uint32_t*)&h01;
        hip[base + 1] = *(uint32_t*)&h23;
        lop[base]     = pack_bf2(lx, ly);
        lop[base + 1] = pack_bf2(lz, lw);
    } else {
        sm4[tid] = acc;
        __syncthreads();
        if (tid < 16) {
            float4 s = make_float4(0.f, 0.f, 0.f, 0.f);
#pragma unroll
            for (int hh = 0; hh < NHEADS; hh++) {
                float4 f = sm4[hh * 16 + tid];
                s.x += f.x; s.y += f.y; s.z += f.z; s.w += f.w;
            }
            float4 b4 = ((const float4*)bias)[tid];
            x3row[tid * 4 + 0] = s.x * (1.0f / NHEADS) + b4.x;
            x3row[tid * 4 + 1] = s.y * (1.0f / NHEADS) + b4.y;
            x3row[tid * 4 + 2] = s.z * (1.0f / NHEADS) + b4.z;
            x3row[tid * 4 + 3] = s.w * (1.0f / NHEADS) + b4.w;
        }
        __syncthreads();
        int o = tid >> 3, c8 = tid & 7;
        float accp = 0.f;
        if (o < OUT_DIM) {
#pragma unroll
            for (int c = 0; c < 8; c++) {
                int cc = c8 * 8 + c;
                accp = fmaf(x3row[cc], __ldg(&Wout[cc * OUT_DIM + o]), accp);
            }
        }
        accp += __shfl_xor_sync(0xffffffffu, accp, 1);
        accp += __shfl_xor_sync(0xffffffffu, accp, 2);
        accp += __shfl_xor_sync(0xffffffffu, accp, 4);
        if (c8 == 0 && o < OUT_DIM)
            outp[(size_t)n * OUT_DIM + o] = accp + __ldg(&bout[o]);
    }
}

// ---------------- launch ----------------
extern "C" void kernel_launch(void* const* d_in, const int* in_sizes, int n_in,
                              void* d_out, int out_size) {
    const float* x    = (const float*)d_in[0];
    const int*   ei   = (const int*)d_in[1];
    const float* W1   = (const float*)d_in[2];
    const float* a1s  = (const float*)d_in[3];
    const float* a1d  = (const float*)d_in[4];
    const float* b1   = (const float*)d_in[5];
    const float* W2   = (const float*)d_in[6];
    const float* a2s  = (const float*)d_in[7];
    const float* a2d  = (const float*)d_in[8];
    const float* b2   = (const float*)d_in[9];
    const float* W3   = (const float*)d_in[10];
    const float* a3s  = (const float*)d_in[11];
    const float* a3d  = (const float*)d_in[12];
    const float* b3   = (const float*)d_in[13];
    const float* Wout = (const float*)d_in[14];
    const float* bout = (const float*)d_in[15];
    float* out = (float*)d_out;

    __half *p_h;
    __nv_bfloat16 *p_xhi, *p_xlo, *p_w2hi, *p_w2lo, *p_w3hi, *p_w3lo;
    cudaGetSymbolAddress((void**)&p_h,    g_h);
    cudaGetSymbolAddress((void**)&p_xhi,  g_xhi);
    cudaGetSymbolAddress((void**)&p_xlo,  g_xlo);
    cudaGetSymbolAddress((void**)&p_w2hi, g_w2hi);
    cudaGetSymbolAddress((void**)&p_w2lo, g_w2lo);
    cudaGetSymbolAddress((void**)&p_w3hi, g_w3hi);
    cudaGetSymbolAddress((void**)&p_w3lo, g_w3lo);

    cudaFuncSetAttribute(mma_gemm_kernel, cudaFuncAttributeMaxDynamicSharedMemorySize, GSMEM);

    const int scan_blocks = (N_NODES + 1023) / 1024;

    init_detect_kernel<<<(N_NODES + 255) / 256, 256>>>(ei);
    count_kernel<<<(NE + 255) / 256, 256>>>(ei);
    scan_block_kernel<<<scan_blocks, 1024>>>();
    scan_add_kernel<<<scan_blocks, 1024>>>();
    fill_kernel<<<(E_TOT + 255) / 256, 256>>>(ei);

    int wsplit_blocks = (2 * HCDIM * HCDIM + 255) / 256;
    wsplit2_kernel<<<wsplit_blocks, 256>>>(W2, W3, p_w2hi, p_w2lo, p_w3hi, p_w3lo);

    dim3 sgrid(HCDIM / BN, (N_NODES + BM - 1) / BM);
    dim3 mgrid(HCDIM / 128, (N_NODES + 127) / 128);
    int stats_blocks = (N_NODES * 32 + 255) / 256;   // warp per node

    // ---- layer 1 ----
    gemm_small_kernel<<<sgrid, 256>>>(x, W1, a1s, a1d, p_h, N_NODES, F_IN, HCDIM);
    stats_kernel<<<stats_blocks, 256>>>();
    aggregate_kernel<<<N_NODES, 128>>>(p_h, b1, p_xhi, p_xlo, nullptr, nullptr, nullptr, 0);

    // ---- layer 2 ----
    mma_gemm_kernel<<<mgrid, 256, GSMEM>>>(p_xhi, p_xlo, p_w2hi, p_w2lo, a2s, a2d, p_h, N_NODES);
    stats_kernel<<<stats_blocks, 256>>>();
    aggregate_kernel<<<N_NODES, 128>>>(p_h, b2, p_xhi, p_xlo, nullptr, nullptr, nullptr, 0);

    // ---- layer 3 (aggregate + mean + bias + projection fused) ----
    mma_gemm_kernel<<<mgrid, 256, GSMEM>>>(p_xhi, p_xlo, p_w3hi, p_w3lo, a3s, a3d, p_h, N_NODES);
    stats_kernel<<<stats_blocks, 256>>>();
    aggregate_kernel<<<N_NODES, 128>>>(p_h, b3, nullptr, nullptr, Wout, bout, out, 1);
}

// round 15
// speedup vs baseline: 1.0575x; 1.0004x over previous
#include <cuda_runtime.h>
#include <cuda_bf16.h>
#include <cuda_fp16.h>
#include <cstdint>
#include <stdint.h>
#include <math.h>

#define N_NODES 50000
#define F_IN    18
#define NHEADS  8
#define CDIM    64
#define HCDIM   512
#define NE      400000
#define E_TOT   (NE + N_NODES)
#define OUT_DIM 15
#define NEG_SLOPE 0.2f

// ---------------- scratch (static device globals; no runtime allocation) ----------------
__device__ __half g_h [N_NODES * HCDIM];          // post-GEMM features (fp16)
__device__ __nv_bfloat16 g_xhi[N_NODES * HCDIM];
__device__ __nv_bfloat16 g_xlo[N_NODES * HCDIM];
__device__ __nv_bfloat16 g_w2hi[HCDIM * HCDIM];
__device__ __nv_bfloat16 g_w2lo[HCDIM * HCDIM];
__device__ __nv_bfloat16 g_w3hi[HCDIM * HCDIM];
__device__ __nv_bfloat16 g_w3lo[HCDIM * HCDIM];
__device__ float g_as[N_NODES * NHEADS];
__device__ float g_ad[N_NODES * NHEADS];
__device__ float g_C [N_NODES * NHEADS];          // softmax constant: m + log(s+eps)
__device__ float g_alpha[(size_t)E_TOT * NHEADS]; // raw e (LeakyReLU'd logits)
__device__ int   g_src_sorted[E_TOT];
__device__ int   g_rowptr[N_NODES + 1];
__device__ int   g_cursor[N_NODES];
__device__ int   g_counts[N_NODES];
__device__ int   g_part[64];
__device__ int   g_is64;

// ---------------- PTX helpers (portable: sm_80-era features only) ----------------
__device__ __forceinline__ uint32_t smem_u32(const void* p) {
    uint32_t a;
    asm("{ .reg .u64 t; cvta.to.shared.u64 t, %1; cvt.u32.u64 %0, t; }" : "=r"(a) : "l"(p));
    return a;
}
static __device__ __forceinline__ void cp_async16(uint32_t dst, const void* src, int sz) {
    asm volatile("cp.async.cg.shared.global [%0], [%1], 16, %2;\n"
                 :: "r"(dst), "l"(src), "r"(sz) : "memory");
}
static __device__ __forceinline__ void cp_commit() {
    asm volatile("cp.async.commit_group;" ::: "memory");
}
static __device__ __forceinline__ void cp_wait0() {
    asm volatile("cp.async.wait_group 0;" ::: "memory");
}
static __device__ __forceinline__ void cp_wait1() {
    asm volatile("cp.async.wait_group 1;" ::: "memory");
}
static __device__ __forceinline__ void cp_wait2() {
    asm volatile("cp.async.wait_group 2;" ::: "memory");
}

#define LDSM_X4(r, addr) \
    asm volatile("ldmatrix.sync.aligned.m8n8.x4.shared.b16 {%0,%1,%2,%3}, [%4];" \
        : "=r"((r)[0]), "=r"((r)[1]), "=r"((r)[2]), "=r"((r)[3]) : "r"(addr))
#define LDSM_X4_TRANS(r, addr) \
    asm volatile("ldmatrix.sync.aligned.m8n8.x4.trans.shared.b16 {%0,%1,%2,%3}, [%4];" \
        : "=r"((r)[0]), "=r"((r)[1]), "=r"((r)[2]), "=r"((r)[3]) : "r"(addr))
#define MMA_BF16(c, a, b) \
    asm volatile("mma.sync.aligned.m16n8k16.row.col.f32.bf16.bf16.f32 " \
        "{%0,%1,%2,%3},{%4,%5,%6,%7},{%8,%9},{%0,%1,%2,%3};" \
        : "+f"((c)[0]), "+f"((c)[1]), "+f"((c)[2]), "+f"((c)[3]) \
        : "r"((a)[0]), "r"((a)[1]), "r"((a)[2]), "r"((a)[3]), "r"((b)[0]), "r"((b)[1]))

// ---------------- edge dtype handling ----------------
__device__ __forceinline__ int edge_at(const int* p, int idx) {
    return g_is64 ? p[2 * idx] : p[idx];
}

// ---------------- CSR build (5 kernels) ----------------
__global__ void init_detect_kernel(const int* __restrict__ p) {
    int i = blockIdx.x * blockDim.x + threadIdx.x;
    if (i < N_NODES) g_counts[i] = 1;
    if (blockIdx.x == 0) {
        __shared__ int red[256];
        int acc = 0;
        for (int k = threadIdx.x; k < 8192; k += 256) acc |= p[2 * k + 1];
        red[threadIdx.x] = acc;
        __syncthreads();
        for (int s = 128; s > 0; s >>= 1) {
            if (threadIdx.x < s) red[threadIdx.x] |= red[threadIdx.x + s];
            __syncthreads();
        }
        if (threadIdx.x == 0) g_is64 = (red[0] == 0) ? 1 : 0;
    }
}
__global__ void count_kernel(const int* __restrict__ ei) {
    int i = blockIdx.x * blockDim.x + threadIdx.x;
    if (i < NE) atomicAdd(&g_counts[edge_at(ei, NE + i)], 1);
}
__global__ void __launch_bounds__(1024) scan_block_kernel() {
    __shared__ int sm[1024];
    int i = blockIdx.x * 1024 + threadIdx.x;
    int v = (i < N_NODES) ? g_counts[i] : 0;
    sm[threadIdx.x] = v;
    __syncthreads();
    for (int off = 1; off < 1024; off <<= 1) {
        int t = (threadIdx.x >= off) ? sm[threadIdx.x - off] : 0;
        __syncthreads();
        sm[threadIdx.x] += t;
        __syncthreads();
    }
    if (i < N_NODES) g_rowptr[i] = sm[threadIdx.x] - v;
    if (threadIdx.x == 1023) g_part[blockIdx.x] = sm[1023];
}
__global__ void __launch_bounds__(1024) scan_add_kernel() {
    __shared__ int base_s;
    if (threadIdx.x == 0) {
        int run = 0;
        for (int b = 0; b < (int)blockIdx.x; b++) run += g_part[b];
        base_s = run;
    }
    __syncthreads();
    int i = blockIdx.x * 1024 + threadIdx.x;
    if (i < N_NODES) {
        int v = g_rowptr[i] + base_s;
        g_rowptr[i] = v;
        g_cursor[i] = v;
    }
    if (i == 0) g_rowptr[N_NODES] = E_TOT;
}
__global__ void fill_kernel(const int* __restrict__ ei) {
    int i = blockIdx.x * blockDim.x + threadIdx.x;
    if (i >= E_TOT) return;
    int src, dst;
    if (i < NE) { src = edge_at(ei, i); dst = edge_at(ei, NE + i); }
    else        { src = dst = i - NE; }
    int pos = atomicAdd(&g_cursor[dst], 1);
    g_src_sorted[pos] = src;
}

// ---------------- small-K GEMM (layer 1, K=18) with fused alpha epilogue ----------------
#define BM 128
#define BN 64
#define BK 16

__global__ void __launch_bounds__(256) gemm_small_kernel(const float* __restrict__ A,
                                                         const float* __restrict__ B,
                                                         const float* __restrict__ a_src,
                                                         const float* __restrict__ a_dst,
                                                         __half* __restrict__ C,
                                                         int M, int K, int Nc) {
    __shared__ float As[BK][BM + 4];
    __shared__ float Bs[BK][BN + 4];
    int tid = threadIdx.x;
    int bn0 = blockIdx.x * BN;
    int bm0 = blockIdx.y * BM;
    int tr = tid >> 4;
    int tc = tid & 15;
    int a_row = tid >> 1;
    int a_cb  = (tid & 1) * 8;
    int b_row = tid >> 4;
    int b_col = (tid & 15) * 4;

    float acc[8][4];
#pragma unroll
    for (int i = 0; i < 8; i++)
#pragma unroll
        for (int j = 0; j < 4; j++) acc[i][j] = 0.f;

    for (int k0 = 0; k0 < K; k0 += BK) {
        int gm = bm0 + a_row;
#pragma unroll
        for (int i = 0; i < 8; i++) {
            int gk = k0 + a_cb + i;
            As[a_cb + i][a_row] = (gm < M && gk < K) ? A[(long long)gm * K + gk] : 0.f;
        }
        {
            int gk = k0 + b_row;
            float4 bv = make_float4(0.f, 0.f, 0.f, 0.f);
            if (gk < K) bv = *(const float4*)&B[(long long)gk * Nc + bn0 + b_col];
            *(float4*)&Bs[b_row][b_col] = bv;
        }
        __syncthreads();
#pragma unroll
        for (int kk = 0; kk < BK; kk++) {
            float a[8], b[4];
#pragma unroll
            for (int i = 0; i < 8; i++) a[i] = As[kk][tr * 8 + i];
#pragma unroll
            for (int j = 0; j < 4; j++) b[j] = Bs[kk][tc * 4 + j];
#pragma unroll
            for (int i = 0; i < 8; i++)
#pragma unroll
                for (int j = 0; j < 4; j++) acc[i][j] += a[i] * b[j];
        }
        __syncthreads();
    }
#pragma unroll
    for (int i = 0; i < 8; i++) {
        int gm = bm0 + tr * 8 + i;
        if (gm < M) {
            __half2 h01 = __floats2half2_rn(acc[i][0], acc[i][1]);
            __half2 h23 = __floats2half2_rn(acc[i][2], acc[i][3]);
            uint2 u;
            u.x = *(uint32_t*)&h01;
            u.y = *(uint32_t*)&h23;
            *(uint2*)&C[(size_t)gm * Nc + bn0 + tc * 4] = u;
        }
    }

    // fused alpha for this head
    {
        int hh = blockIdx.x;
        float pas[8], pad_[8];
#pragma unroll
        for (int i = 0; i < 8; i++) { pas[i] = 0.f; pad_[i] = 0.f; }
#pragma unroll
        for (int j = 0; j < 4; j++) {
            float sj = __ldg(&a_src[hh * CDIM + tc * 4 + j]);
            float dj = __ldg(&a_dst[hh * CDIM + tc * 4 + j]);
#pragma unroll
            for (int i = 0; i < 8; i++) {
                pas[i]  = fmaf(acc[i][j], sj, pas[i]);
                pad_[i] = fmaf(acc[i][j], dj, pad_[i]);
            }
        }
#pragma unroll
        for (int off = 1; off < 16; off <<= 1) {
#pragma unroll
            for (int i = 0; i < 8; i++) {
                pas[i]  += __shfl_xor_sync(0xffffffffu, pas[i], off);
                pad_[i] += __shfl_xor_sync(0xffffffffu, pad_[i], off);
            }
        }
        if (tc == 0) {
#pragma unroll
            for (int i = 0; i < 8; i++) {
                int gm = bm0 + tr * 8 + i;
                if (gm < M) {
                    g_as[gm * NHEADS + hh] = pas[i];
                    g_ad[gm * NHEADS + hh] = pad_[i];
                }
            }
        }
    }
}

// ---------------- W bf16 split (both W2 and W3 in one launch) ----------------
__global__ void __launch_bounds__(256) wsplit2_kernel(const float* __restrict__ W2,
                                                      const float* __restrict__ W3,
                                                      __nv_bfloat16* __restrict__ w2hi,
                                                      __nv_bfloat16* __restrict__ w2lo,
                                                      __nv_bfloat16* __restrict__ w3hi,
                                                      __nv_bfloat16* __restrict__ w3lo) {
    int i = blockIdx.x * blockDim.x + threadIdx.x;
    const int NW = HCDIM * HCDIM;
    if (i < NW) {
        float v = W2[i];
        __nv_bfloat16 hi = __float2bfloat16_rn(v);
        w2hi[i] = hi;
        w2lo[i] = __float2bfloat16_rn(v - __bfloat162float(hi));
    } else if (i < 2 * NW) {
        int k = i - NW;
        float v = W3[k];
        __nv_bfloat16 hi = __float2bfloat16_rn(v);
        w3hi[k] = hi;
        w3lo[k] = __float2bfloat16_rn(v - __bfloat162float(hi));
    }
}

// ---------------- mma.sync bf16-split GEMM + fused alpha epilogue, 3-stage pipeline ----
#define KTILES  (HCDIM / 32)      // 16
#define APITCH  80
#define BPITCH  272
#define A_TB    (128 * APITCH)
#define B_TB    (32 * BPITCH)
#define BUF_B   (2 * A_TB + 2 * B_TB)   // 37888
#define NSTAGE  3
#define GSMEM   (NSTAGE * BUF_B)        // 113664; 2 CTAs/SM = 227328 <= 228KB

__global__ void __launch_bounds__(256, 2)
mma_gemm_kernel(const __nv_bfloat16* __restrict__ Ahi,
                const __nv_bfloat16* __restrict__ Alo,
                const __nv_bfloat16* __restrict__ Whi,
                const __nv_bfloat16* __restrict__ Wlo,
                const float* __restrict__ a_src,
                const float* __restrict__ a_dst,
                __half* __restrict__ C, int M) {
    extern __shared__ char smem[];
    uint32_t sb = smem_u32(smem);
    int tid = threadIdx.x, lane = tid & 31, wid = tid >> 5;
    int wm = wid & 3, wn = wid >> 2;
    int bm0 = blockIdx.y * 128, bn0 = blockIdx.x * 128;

    float acc[2][8][4];
#pragma unroll
    for (int im = 0; im < 2; im++)
#pragma unroll
        for (int in_ = 0; in_ < 8; in_++)
#pragma unroll
            for (int q = 0; q < 4; q++) acc[im][in_][q] = 0.f;

    auto load_tile = [&](int kt, int b) {
        uint32_t base = sb + (uint32_t)b * BUF_B;
#pragma unroll
        for (int m = 0; m < 2; m++) {
            const __nv_bfloat16* srcm = m ? Alo : Ahi;
            uint32_t tb = base + (uint32_t)m * A_TB;
#pragma unroll
            for (int q = 0; q < 2; q++) {
                int idx = q * 256 + tid;
                int r = idx >> 2, ch = idx & 3;
                int gr = bm0 + r;
                int sz = 16;
                if (gr >= M) { gr = 0; sz = 0; }
                cp_async16(tb + (uint32_t)(r * APITCH + ch * 16),
                           srcm + (size_t)gr * HCDIM + kt * 32 + ch * 8, sz);
            }
        }
#pragma unroll
        for (int m = 0; m < 2; m++) {
            const __nv_bfloat16* srcm = m ? Wlo : Whi;
            uint32_t tb = base + 2 * A_TB + (uint32_t)m * B_TB;
#pragma unroll
            for (int q = 0; q < 2; q++) {
                int idx = q * 256 + tid;
                int r = idx >> 4, ch = idx & 15;
                cp_async16(tb + (uint32_t)(r * BPITCH + ch * 16),
                           srcm + (size_t)(kt * 32 + r) * HCDIM + bn0 + ch * 8, 16);
            }
        }
        cp_commit();
    };

    // prologue: two tiles in flight
    load_tile(0, 0);
    load_tile(1, 1);

    for (int t = 0; t < KTILES; t++) {
        int b = t % NSTAGE;
        if (t + 2 < KTILES) { load_tile(t + 2, (t + 2) % NSTAGE); cp_wait2(); }
        else if (t + 1 < KTILES) cp_wait1();
        else cp_wait0();
        __syncthreads();

        uint32_t abase = sb + (uint32_t)b * BUF_B;
        uint32_t bbase = abase + 2 * A_TB;
#pragma unroll
        for (int ks = 0; ks < 2; ks++) {
            uint32_t ah[2][4], al[2][4];
#pragma unroll
            for (int im = 0; im < 2; im++) {
                uint32_t ra = abase
                    + (uint32_t)((wm * 32 + im * 16 + (lane & 15)) * APITCH
                                 + (ks * 16 + (lane >> 4) * 8) * 2);
                LDSM_X4(ah[im], ra);
                LDSM_X4(al[im], ra + A_TB);
            }
            int g = lane >> 3;
#pragma unroll
            for (int in2 = 0; in2 < 4; in2++) {
                uint32_t rb = bbase
                    + (uint32_t)((ks * 16 + (lane & 7) + (g & 1) * 8) * BPITCH
                                 + (wn * 64 + in2 * 16 + (g >> 1) * 8) * 2);
                uint32_t bh[4], bl[4];
                LDSM_X4_TRANS(bh, rb);
                LDSM_X4_TRANS(bl, rb + B_TB);
#pragma unroll
                for (int im = 0; im < 2; im++) {
                    MMA_BF16(acc[im][in2 * 2],     ah[im], (bh + 0));
                    MMA_BF16(acc[im][in2 * 2],     ah[im], (bl + 0));
                    MMA_BF16(acc[im][in2 * 2],     al[im], (bh + 0));
                    MMA_BF16(acc[im][in2 * 2 + 1], ah[im], (bh + 2));
                    MMA_BF16(acc[im][in2 * 2 + 1], ah[im], (bl + 2));
                    MMA_BF16(acc[im][in2 * 2 + 1], al[im], (bh + 2));
                }
            }
        }
        __syncthreads();
    }

    // ---- C store (fp16) ----
#pragma unroll
    for (int im = 0; im < 2; im++) {
        int r0 = bm0 + wm * 32 + im * 16 + (lane >> 2);
#pragma unroll
        for (int in_ = 0; in_ < 8; in_++) {
            int col = bn0 + wn * 64 + in_ * 8 + (lane & 3) * 2;
            if (r0 < M) {
                __half2 hp = __floats2half2_rn(acc[im][in_][0], acc[im][in_][1]);
                *(uint32_t*)&C[(size_t)r0 * HCDIM + col] = *(uint32_t*)&hp;
            }
            if (r0 + 8 < M) {
                __half2 hp = __floats2half2_rn(acc[im][in_][2], acc[im][in_][3]);
                *(uint32_t*)&C[(size_t)(r0 + 8) * HCDIM + col] = *(uint32_t*)&hp;
            }
        }
    }

    // ---- fused alpha: warp's 64 cols = one head ----
    {
        int hh = (bn0 >> 6) + wn;
        float pas[4] = {0.f, 0.f, 0.f, 0.f};
        float pad_[4] = {0.f, 0.f, 0.f, 0.f};
#pragma unroll
        for (int in_ = 0; in_ < 8; in_++) {
            int c0 = in_ * 8 + (lane & 3) * 2;
            float s0 = __ldg(&a_src[hh * CDIM + c0]);
            float s1 = __ldg(&a_src[hh * CDIM + c0 + 1]);
            float d0 = __ldg(&a_dst[hh * CDIM + c0]);
            float d1 = __ldg(&a_dst[hh * CDIM + c0 + 1]);
#pragma unroll
            for (int im = 0; im < 2; im++) {
                pas[im * 2]     += acc[im][in_][0] * s0 + acc[im][in_][1] * s1;
                pas[im * 2 + 1] += acc[im][in_][2] * s0 + acc[im][in_][3] * s1;
                pad_[im * 2]     += acc[im][in_][0] * d0 + acc[im][in_][1] * d1;
                pad_[im * 2 + 1] += acc[im][in_][2] * d0 + acc[im][in_][3] * d1;
            }
        }
#pragma unroll
        for (int k = 0; k < 4; k++) {
            pas[k]  += __shfl_xor_sync(0xffffffffu, pas[k], 1);
            pas[k]  += __shfl_xor_sync(0xffffffffu, pas[k], 2);
            pad_[k] += __shfl_xor_sync(0xffffffffu, pad_[k], 1);
            pad_[k] += __shfl_xor_sync(0xffffffffu, pad_[k], 2);
        }
        if ((lane & 3) == 0) {
#pragma unroll
            for (int im = 0; im < 2; im++) {
                int r0 = bm0 + wm * 32 + im * 16 + (lane >> 2);
                if (r0 < M) {
                    g_as[r0 * NHEADS + hh] = pas[im * 2];
                    g_ad[r0 * NHEADS + hh] = pad_[im * 2];
                }
                if (r0 + 8 < M) {
                    g_as[(r0 + 8) * NHEADS + hh] = pas[im * 2 + 1];
                    g_ad[(r0 + 8) * NHEADS + hh] = pad_[im * 2 + 1];
                }
            }
        }
    }
}

// ---------------- segment softmax: warp per node, 4 edges x 8 heads per iter ----------------
__global__ void stats_kernel() {
    int lane = threadIdx.x & 31;
    int n = (blockIdx.x * blockDim.x + threadIdx.x) >> 5;
    int hh = lane & 7, sub = lane >> 3;
    if (n >= N_NODES) return;
    int row = g_rowptr[n], end = g_rowptr[n + 1];
    float ad = g_ad[n * NHEADS + hh];
    float m = -1e30f, s = 0.f;
    for (int j = row + sub; j < end; j += 4) {
        int src = g_src_sorted[j];
        float e = g_as[src * NHEADS + hh] + ad;
        e = (e > 0.f) ? e : NEG_SLOPE * e;
        g_alpha[(size_t)j * NHEADS + hh] = e;
        float nm = fmaxf(m, e);
        s = s * __expf(m - nm) + __expf(e - nm);
        m = nm;
    }
#pragma unroll
    for (int off = 8; off <= 16; off <<= 1) {
        float mo = __shfl_xor_sync(0xffffffffu, m, off);
        float so = __shfl_xor_sync(0xffffffffu, s, off);
        float nm = fmaxf(m, mo);
        s = s * __expf(m - nm) + so * __expf(mo - nm);
        m = nm;
    }
    if (sub == 0) g_C[n * NHEADS + hh] = m + __logf(s + 1e-16f);
}

// ---------------- heavy aggregation (fp16 h, alpha inline; mode 1 fuses projection) -----
__device__ __forceinline__ uint32_t pack_bf2(float a, float b) {
    __nv_bfloat162 t;
    t.x = __float2bfloat16_rn(a);
    t.y = __float2bfloat16_rn(b);
    return *(uint32_t*)&t;
}

__global__ void __launch_bounds__(128) aggregate_kernel(const __half* __restrict__ hin,
                                                        const float* __restrict__ bias,
                                                        __nv_bfloat16* __restrict__ xhi,
                                                        __nv_bfloat16* __restrict__ xlo,
                                                        const float* __restrict__ Wout,
                                                        const float* __restrict__ bout,
                                                        float* __restrict__ outp,
                                                        int mode) {
    __shared__ float4 sm4[HCDIM / 4];
    __shared__ float x3row[CDIM];
    int n = blockIdx.x;
    int tid = threadIdx.x;
    int head = tid >> 4;
    int row = g_rowptr[n], end = g_rowptr[n + 1];
    float Cc = __ldg(&g_C[n * NHEADS + head]);
    const uint2* h2 = (const uint2*)hin;
    float4 acc = make_float4(0.f, 0.f, 0.f, 0.f);
    int j = row;
    for (; j + 3 < end; j += 4) {
        int s0 = __ldg(&g_src_sorted[j]);
        int s1 = __ldg(&g_src_sorted[j + 1]);
        int s2 = __ldg(&g_src_sorted[j + 2]);
        int s3 = __ldg(&g_src_sorted[j + 3]);
        float a0 = __expf(__ldg(&g_alpha[(size_t)j * NHEADS + head]) - Cc);
        float a1 = __expf(__ldg(&g_alpha[(size_t)(j + 1) * NHEADS + head]) - Cc);
        float a2 = __expf(__ldg(&g_alpha[(size_t)(j + 2) * NHEADS + head]) - Cc);
        float a3 = __expf(__ldg(&g_alpha[(size_t)(j + 3) * NHEADS + head]) - Cc);
        uint2 u0 = __ldg(&h2[(size_t)s0 * (HCDIM / 4) + tid]);
        uint2 u1 = __ldg(&h2[(size_t)s1 * (HCDIM / 4) + tid]);
        uint2 u2 = __ldg(&h2[(size_t)s2 * (HCDIM / 4) + tid]);
        uint2 u3 = __ldg(&h2[(size_t)s3 * (HCDIM / 4) + tid]);
        float2 f0a = __half22float2(*(__half2*)&u0.x), f0b = __half22float2(*(__half2*)&u0.y);
        float2 f1a = __half22float2(*(__half2*)&u1.x), f1b = __half22float2(*(__half2*)&u1.y);
        float2 f2a = __half22float2(*(__half2*)&u2.x), f2b = __half22float2(*(__half2*)&u2.y);
        float2 f3a = __half22float2(*(__half2*)&u3.x), f3b = __half22float2(*(__half2*)&u3.y);
        acc.x = fmaf(a0, f0a.x, fmaf(a1, f1a.x, fmaf(a2, f2a.x, fmaf(a3, f3a.x, acc.x))));
        acc.y = fmaf(a0, f0a.y, fmaf(a1, f1a.y, fmaf(a2, f2a.y, fmaf(a3, f3a.y, acc.y))));
        acc.z = fmaf(a0, f0b.x, fmaf(a1, f1b.x, fmaf(a2, f2b.x, fmaf(a3, f3b.x, acc.z))));
        acc.w = fmaf(a0, f0b.y, fmaf(a1, f1b.y, fmaf(a2, f2b.y, fmaf(a3, f3b.y, acc.w))));
    }
    for (; j < end; j++) {
        int s0 = __ldg(&g_src_sorted[j]);
        float a0 = __expf(__ldg(&g_alpha[(size_t)j * NHEADS + head]) - Cc);
        uint2 u0 = __ldg(&h2[(size_t)s0 * (HCDIM / 4) + tid]);
        float2 f0a = __half22float2(*(__half2*)&u0.x);
        float2 f0b = __half22float2(*(__half2*)&u0.y);
        acc.x = fmaf(a0, f0a.x, acc.x);
        acc.y = fmaf(a0, f0a.y, acc.y);
        acc.z = fmaf(a0, f0b.x, acc.z);
        acc.w = fmaf(a0, f0b.y, acc.w);
    }
    if (mode == 0) {
        float4 b4 = ((const float4*)bias)[tid];
        float vx = acc.x + b4.x; vx = (vx > 0.f) ? vx : expm1f(vx);
        float vy = acc.y + b4.y; vy = (vy > 0.f) ? vy : expm1f(vy);
        float vz = acc.z + b4.z; vz = (vz > 0.f) ? vz : expm1f(vz);
        float vw = acc.w + b4.w; vw = (vw > 0.f) ? vw : expm1f(vw);
        __nv_bfloat16 hx = __float2bfloat16_rn(vx), hy = __float2bfloat16_rn(vy);
        __nv_bfloat16 hz = __float2bfloat16_rn(vz), hw = __float2bfloat16_rn(vw);
        float lx = vx - __bfloat162float(hx), ly = vy - __bfloat162float(hy);
        float lz = vz - __bfloat162float(hz), lw = vw - __bfloat162float(hw);
        size_t base = ((size_t)n * HCDIM + tid * 4) >> 1;
        uint32_t* hip = (uint32_t*)xhi;
        uint32_t* lop = (uint32_t*)xlo;
        __nv_bfloat162 h01; h01.x = hx; h01.y = hy;
        __nv_bfloat162 h23; h23.x = hz; h23.y = hw;
        hip[base]     = *(uint32_t*)&h01;
        hip[base + 1] = *(uint32_t*)&h23;
        lop[base]     = pack_bf2(lx, ly);
        lop[base + 1] = pack_bf2(lz, lw);
    } else {
        sm4[tid] = acc;
        __syncthreads();
        if (tid < 16) {
            float4 s = make_float4(0.f, 0.f, 0.f, 0.f);
#pragma unroll
            for (int hh = 0; hh < NHEADS; hh++) {
                float4 f = sm4[hh * 16 + tid];
                s.x += f.x; s.y += f.y; s.z += f.z; s.w += f.w;
            }
            float4 b4 = ((const float4*)bias)[tid];
            x3row[tid * 4 + 0] = s.x * (1.0f / NHEADS) + b4.x;
            x3row[tid * 4 + 1] = s.y * (1.0f / NHEADS) + b4.y;
            x3row[tid * 4 + 2] = s.z * (1.0f / NHEADS) + b4.z;
            x3row[tid * 4 + 3] = s.w * (1.0f / NHEADS) + b4.w;
        }
        __syncthreads();
        int o = tid >> 3, c8 = tid & 7;
        float accp = 0.f;
        if (o < OUT_DIM) {
#pragma unroll
            for (int c = 0; c < 8; c++) {
                int cc = c8 * 8 + c;
                accp = fmaf(x3row[cc], __ldg(&Wout[cc * OUT_DIM + o]), accp);
            }
        }
        accp += __shfl_xor_sync(0xffffffffu, accp, 1);
        accp += __shfl_xor_sync(0xffffffffu, accp, 2);
        accp += __shfl_xor_sync(0xffffffffu, accp, 4);
        if (c8 == 0 && o < OUT_DIM)
            outp[(size_t)n * OUT_DIM + o] = accp + __ldg(&bout[o]);
    }
}

// ---------------- launch ----------------
extern "C" void kernel_launch(void* const* d_in, const int* in_sizes, int n_in,
                              void* d_out, int out_size) {
    const float* x    = (const float*)d_in[0];
    const int*   ei   = (const int*)d_in[1];
    const float* W1   = (const float*)d_in[2];
    const float* a1s  = (const float*)d_in[3];
    const float* a1d  = (const float*)d_in[4];
    const float* b1   = (const float*)d_in[5];
    const float* W2   = (const float*)d_in[6];
    const float* a2s  = (const float*)d_in[7];
    const float* a2d  = (const float*)d_in[8];
    const float* b2   = (const float*)d_in[9];
    const float* W3   = (const float*)d_in[10];
    const float* a3s  = (const float*)d_in[11];
    const float* a3d  = (const float*)d_in[12];
    const float* b3   = (const float*)d_in[13];
    const float* Wout = (const float*)d_in[14];
    const float* bout = (const float*)d_in[15];
    float* out = (float*)d_out;

    __half *p_h;
    __nv_bfloat16 *p_xhi, *p_xlo, *p_w2hi, *p_w2lo, *p_w3hi, *p_w3lo;
    cudaGetSymbolAddress((void**)&p_h,    g_h);
    cudaGetSymbolAddress((void**)&p_xhi,  g_xhi);
    cudaGetSymbolAddress((void**)&p_xlo,  g_xlo);
    cudaGetSymbolAddress((void**)&p_w2hi, g_w2hi);
    cudaGetSymbolAddress((void**)&p_w2lo, g_w2lo);
    cudaGetSymbolAddress((void**)&p_w3hi, g_w3hi);
    cudaGetSymbolAddress((void**)&p_w3lo, g_w3lo);

    cudaFuncSetAttribute(mma_gemm_kernel, cudaFuncAttributeMaxDynamicSharedMemorySize, GSMEM);

    const int scan_blocks = (N_NODES + 1023) / 1024;

    init_detect_kernel<<<(N_NODES + 255) / 256, 256>>>(ei);
    count_kernel<<<(NE + 255) / 256, 256>>>(ei);
    scan_block_kernel<<<scan_blocks, 1024>>>();
    scan_add_kernel<<<scan_blocks, 1024>>>();
    fill_kernel<<<(E_TOT + 255) / 256, 256>>>(ei);

    int wsplit_blocks = (2 * HCDIM * HCDIM + 255) / 256;
    wsplit2_kernel<<<wsplit_blocks, 256>>>(W2, W3, p_w2hi, p_w2lo, p_w3hi, p_w3lo);

    dim3 sgrid(HCDIM / BN, (N_NODES + BM - 1) / BM);
    dim3 mgrid(HCDIM / 128, (N_NODES + 127) / 128);
    int stats_blocks = (N_NODES * 32 + 255) / 256;   // warp per node

    // ---- layer 1 ----
    gemm_small_kernel<<<sgrid, 256>>>(x, W1, a1s, a1d, p_h, N_NODES, F_IN, HCDIM);
    stats_kernel<<<stats_blocks, 256>>>();
    aggregate_kernel<<<N_NODES, 128>>>(p_h, b1, p_xhi, p_xlo, nullptr, nullptr, nullptr, 0);

    // ---- layer 2 ----
    mma_gemm_kernel<<<mgrid, 256, GSMEM>>>(p_xhi, p_xlo, p_w2hi, p_w2lo, a2s, a2d, p_h, N_NODES);
    stats_kernel<<<stats_blocks, 256>>>();
    aggregate_kernel<<<N_NODES, 128>>>(p_h, b2, p_xhi, p_xlo, nullptr, nullptr, nullptr, 0);

    // ---- layer 3 (aggregate + mean + bias + projection fused) ----
    mma_gemm_kernel<<<mgrid, 256, GSMEM>>>(p_xhi, p_xlo, p_w3hi, p_w3lo, a3s, a3d, p_h, N_NODES);
    stats_kernel<<<stats_blocks, 256>>>();
    aggregate_kernel<<<N_NODES, 128>>>(p_h, b3, nullptr, nullptr, Wout, bout, out, 1);
}

// round 16
// speedup vs baseline: 1.2219x; 1.1554x over previous
#include <cuda_runtime.h>
#include <cuda_bf16.h>
#include <cuda_fp16.h>
#include <cstdint>
#include <stdint.h>
#include <math.h>

#define N_NODES 50000
#define F_IN    18
#define NHEADS  8
#define CDIM    64
#define HCDIM   512
#define NE      400000
#define E_TOT   (NE + N_NODES)
#define OUT_DIM 15
#define NEG_SLOPE 0.2f

// ---------------- scratch (static device globals; no runtime allocation) ----------------
__device__ __half g_h [N_NODES * HCDIM];          // post-GEMM features (fp16)
__device__ __half g_xhi[N_NODES * HCDIM];         // activation hi (fp16)
__device__ __half g_xlo[N_NODES * HCDIM];         // activation lo (fp16 residual)
__device__ __half g_w2[HCDIM * HCDIM];            // W2 fp16 (no split needed)
__device__ __half g_w3[HCDIM * HCDIM];
__device__ float g_as[N_NODES * NHEADS];
__device__ float g_ad[N_NODES * NHEADS];
__device__ float g_C [N_NODES * NHEADS];          // softmax constant: m + log(s+eps)
__device__ float g_alpha[(size_t)E_TOT * NHEADS]; // raw e (LeakyReLU'd logits)
__device__ int   g_src_sorted[E_TOT];
__device__ int   g_rowptr[N_NODES + 1];
__device__ int   g_cursor[N_NODES];
__device__ int   g_counts[N_NODES];
__device__ int   g_part[64];
__device__ int   g_is64;

// ---------------- PTX helpers (portable: sm_80-era features only) ----------------
__device__ __forceinline__ uint32_t smem_u32(const void* p) {
    uint32_t a;
    asm("{ .reg .u64 t; cvta.to.shared.u64 t, %1; cvt.u32.u64 %0, t; }" : "=r"(a) : "l"(p));
    return a;
}
static __device__ __forceinline__ void cp_async16(uint32_t dst, const void* src, int sz) {
    asm volatile("cp.async.cg.shared.global [%0], [%1], 16, %2;\n"
                 :: "r"(dst), "l"(src), "r"(sz) : "memory");
}
static __device__ __forceinline__ void cp_commit() {
    asm volatile("cp.async.commit_group;" ::: "memory");
}
static __device__ __forceinline__ void cp_wait0() {
    asm volatile("cp.async.wait_group 0;" ::: "memory");
}
static __device__ __forceinline__ void cp_wait1() {
    asm volatile("cp.async.wait_group 1;" ::: "memory");
}
static __device__ __forceinline__ void cp_wait2() {
    asm volatile("cp.async.wait_group 2;" ::: "memory");
}

#define LDSM_X4(r, addr) \
    asm volatile("ldmatrix.sync.aligned.m8n8.x4.shared.b16 {%0,%1,%2,%3}, [%4];" \
        : "=r"((r)[0]), "=r"((r)[1]), "=r"((r)[2]), "=r"((r)[3]) : "r"(addr))
#define LDSM_X4_TRANS(r, addr) \
    asm volatile("ldmatrix.sync.aligned.m8n8.x4.trans.shared.b16 {%0,%1,%2,%3}, [%4];" \
        : "=r"((r)[0]), "=r"((r)[1]), "=r"((r)[2]), "=r"((r)[3]) : "r"(addr))
#define MMA_F16(c, a, b) \
    asm volatile("mma.sync.aligned.m16n8k16.row.col.f32.f16.f16.f32 " \
        "{%0,%1,%2,%3},{%4,%5,%6,%7},{%8,%9},{%0,%1,%2,%3};" \
        : "+f"((c)[0]), "+f"((c)[1]), "+f"((c)[2]), "+f"((c)[3]) \
        : "r"((a)[0]), "r"((a)[1]), "r"((a)[2]), "r"((a)[3]), "r"((b)[0]), "r"((b)[1]))

// ---------------- edge dtype handling ----------------
__device__ __forceinline__ int edge_at(const int* p, int idx) {
    return g_is64 ? p[2 * idx] : p[idx];
}

// ---------------- CSR build (5 kernels) ----------------
__global__ void init_detect_kernel(const int* __restrict__ p) {
    int i = blockIdx.x * blockDim.x + threadIdx.x;
    if (i < N_NODES) g_counts[i] = 1;
    if (blockIdx.x == 0) {
        __shared__ int red[256];
        int acc = 0;
        for (int k = threadIdx.x; k < 8192; k += 256) acc |= p[2 * k + 1];
        red[threadIdx.x] = acc;
        __syncthreads();
        for (int s = 128; s > 0; s >>= 1) {
            if (threadIdx.x < s) red[threadIdx.x] |= red[threadIdx.x + s];
            __syncthreads();
        }
        if (threadIdx.x == 0) g_is64 = (red[0] == 0) ? 1 : 0;
    }
}
__global__ void count_kernel(const int* __restrict__ ei) {
    int i = blockIdx.x * blockDim.x + threadIdx.x;
    if (i < NE) atomicAdd(&g_counts[edge_at(ei, NE + i)], 1);
}
__global__ void __launch_bounds__(1024) scan_block_kernel() {
    __shared__ int sm[1024];
    int i = blockIdx.x * 1024 + threadIdx.x;
    int v = (i < N_NODES) ? g_counts[i] : 0;
    sm[threadIdx.x] = v;
    __syncthreads();
    for (int off = 1; off < 1024; off <<= 1) {
        int t = (threadIdx.x >= off) ? sm[threadIdx.x - off] : 0;
        __syncthreads();
        sm[threadIdx.x] += t;
        __syncthreads();
    }
    if (i < N_NODES) g_rowptr[i] = sm[threadIdx.x] - v;
    if (threadIdx.x == 1023) g_part[blockIdx.x] = sm[1023];
}
__global__ void __launch_bounds__(1024) scan_add_kernel() {
    __shared__ int base_s;
    if (threadIdx.x == 0) {
        int run = 0;
        for (int b = 0; b < (int)blockIdx.x; b++) run += g_part[b];
        base_s = run;
    }
    __syncthreads();
    int i = blockIdx.x * 1024 + threadIdx.x;
    if (i < N_NODES) {
        int v = g_rowptr[i] + base_s;
        g_rowptr[i] = v;
        g_cursor[i] = v;
    }
    if (i == 0) g_rowptr[N_NODES] = E_TOT;
}
__global__ void fill_kernel(const int* __restrict__ ei) {
    int i = blockIdx.x * blockDim.x + threadIdx.x;
    if (i >= E_TOT) return;
    int src, dst;
    if (i < NE) { src = edge_at(ei, i); dst = edge_at(ei, NE + i); }
    else        { src = dst = i - NE; }
    int pos = atomicAdd(&g_cursor[dst], 1);
    g_src_sorted[pos] = src;
}

// ---------------- small-K GEMM (layer 1, K=18) with fused alpha epilogue ----------------
#define BM 128
#define BN 64
#define BK 16

__global__ void __launch_bounds__(256) gemm_small_kernel(const float* __restrict__ A,
                                                         const float* __restrict__ B,
                                                         const float* __restrict__ a_src,
                                                         const float* __restrict__ a_dst,
                                                         __half* __restrict__ C,
                                                         int M, int K, int Nc) {
    __shared__ float As[BK][BM + 4];
    __shared__ float Bs[BK][BN + 4];
    int tid = threadIdx.x;
    int bn0 = blockIdx.x * BN;
    int bm0 = blockIdx.y * BM;
    int tr = tid >> 4;
    int tc = tid & 15;
    int a_row = tid >> 1;
    int a_cb  = (tid & 1) * 8;
    int b_row = tid >> 4;
    int b_col = (tid & 15) * 4;

    float acc[8][4];
#pragma unroll
    for (int i = 0; i < 8; i++)
#pragma unroll
        for (int j = 0; j < 4; j++) acc[i][j] = 0.f;

    for (int k0 = 0; k0 < K; k0 += BK) {
        int gm = bm0 + a_row;
#pragma unroll
        for (int i = 0; i < 8; i++) {
            int gk = k0 + a_cb + i;
            As[a_cb + i][a_row] = (gm < M && gk < K) ? A[(long long)gm * K + gk] : 0.f;
        }
        {
            int gk = k0 + b_row;
            float4 bv = make_float4(0.f, 0.f, 0.f, 0.f);
            if (gk < K) bv = *(const float4*)&B[(long long)gk * Nc + bn0 + b_col];
            *(float4*)&Bs[b_row][b_col] = bv;
        }
        __syncthreads();
#pragma unroll
        for (int kk = 0; kk < BK; kk++) {
            float a[8], b[4];
#pragma unroll
            for (int i = 0; i < 8; i++) a[i] = As[kk][tr * 8 + i];
#pragma unroll
            for (int j = 0; j < 4; j++) b[j] = Bs[kk][tc * 4 + j];
#pragma unroll
            for (int i = 0; i < 8; i++)
#pragma unroll
                for (int j = 0; j < 4; j++) acc[i][j] += a[i] * b[j];
        }
        __syncthreads();
    }
#pragma unroll
    for (int i = 0; i < 8; i++) {
        int gm = bm0 + tr * 8 + i;
        if (gm < M) {
            __half2 h01 = __floats2half2_rn(acc[i][0], acc[i][1]);
            __half2 h23 = __floats2half2_rn(acc[i][2], acc[i][3]);
            uint2 u;
            u.x = *(uint32_t*)&h01;
            u.y = *(uint32_t*)&h23;
            *(uint2*)&C[(size_t)gm * Nc + bn0 + tc * 4] = u;
        }
    }

    // fused alpha for this head
    {
        int hh = blockIdx.x;
        float pas[8], pad_[8];
#pragma unroll
        for (int i = 0; i < 8; i++) { pas[i] = 0.f; pad_[i] = 0.f; }
#pragma unroll
        for (int j = 0; j < 4; j++) {
            float sj = __ldg(&a_src[hh * CDIM + tc * 4 + j]);
            float dj = __ldg(&a_dst[hh * CDIM + tc * 4 + j]);
#pragma unroll
            for (int i = 0; i < 8; i++) {
                pas[i]  = fmaf(acc[i][j], sj, pas[i]);
                pad_[i] = fmaf(acc[i][j], dj, pad_[i]);
            }
        }
#pragma unroll
        for (int off = 1; off < 16; off <<= 1) {
#pragma unroll
            for (int i = 0; i < 8; i++) {
                pas[i]  += __shfl_xor_sync(0xffffffffu, pas[i], off);
                pad_[i] += __shfl_xor_sync(0xffffffffu, pad_[i], off);
            }
        }
        if (tc == 0) {
#pragma unroll
            for (int i = 0; i < 8; i++) {
                int gm = bm0 + tr * 8 + i;
                if (gm < M) {
                    g_as[gm * NHEADS + hh] = pas[i];
                    g_ad[gm * NHEADS + hh] = pad_[i];
                }
            }
        }
    }
}

// ---------------- W fp16 convert (W2 and W3 in one launch; no split needed) -------------
__global__ void __launch_bounds__(256) wconv_kernel(const float* __restrict__ W2,
                                                    const float* __restrict__ W3,
                                                    __half* __restrict__ w2,
                                                    __half* __restrict__ w3) {
    int i = blockIdx.x * blockDim.x + threadIdx.x;
    const int NW = HCDIM * HCDIM;
    if (i < NW)           w2[i]      = __float2half_rn(W2[i]);
    else if (i < 2 * NW)  w3[i - NW] = __float2half_rn(W3[i - NW]);
}

// ---------------- mma.sync fp16 2-product GEMM + fused alpha epilogue, 3-stage ----------
// C = Ahi@W + Alo@W  (A split into fp16 hi + fp16 residual; W in fp16; fp32 accumulate)
#define KTILES  (HCDIM / 32)      // 16
#define APITCH  80
#define BPITCH  272
#define A_TB    (128 * APITCH)    // 10240
#define B_TB    (32 * BPITCH)     // 8704
#define BUF_B   (2 * A_TB + B_TB) // 29184 (Ahi + Alo + W)
#define NSTAGE  3
#define GSMEM   (NSTAGE * BUF_B)  // 87552; 2 CTAs/SM = 175104 <= 228KB

__global__ void __launch_bounds__(256, 2)
mma_gemm_kernel(const __half* __restrict__ Ahi,
                const __half* __restrict__ Alo,
                const __half* __restrict__ W,
                const float* __restrict__ a_src,
                const float* __restrict__ a_dst,
                __half* __restrict__ C, int M) {
    extern __shared__ char smem[];
    uint32_t sb = smem_u32(smem);
    int tid = threadIdx.x, lane = tid & 31, wid = tid >> 5;
    int wm = wid & 3, wn = wid >> 2;
    int bm0 = blockIdx.y * 128, bn0 = blockIdx.x * 128;

    float acc[2][8][4];
#pragma unroll
    for (int im = 0; im < 2; im++)
#pragma unroll
        for (int in_ = 0; in_ < 8; in_++)
#pragma unroll
            for (int q = 0; q < 4; q++) acc[im][in_][q] = 0.f;

    auto load_tile = [&](int kt, int b) {
        uint32_t base = sb + (uint32_t)b * BUF_B;
        // A tiles (hi, lo): 128 rows x 64B each
#pragma unroll
        for (int m = 0; m < 2; m++) {
            const __half* srcm = m ? Alo : Ahi;
            uint32_t tb = base + (uint32_t)m * A_TB;
#pragma unroll
            for (int q = 0; q < 2; q++) {
                int idx = q * 256 + tid;
                int r = idx >> 2, ch = idx & 3;
                int gr = bm0 + r;
                int sz = 16;
                if (gr >= M) { gr = 0; sz = 0; }
                cp_async16(tb + (uint32_t)(r * APITCH + ch * 16),
                           srcm + (size_t)gr * HCDIM + kt * 32 + ch * 8, sz);
            }
        }
        // W tile: 32 k-rows x 256B
        {
            uint32_t tb = base + 2 * A_TB;
#pragma unroll
            for (int q = 0; q < 2; q++) {
                int idx = q * 256 + tid;
                int r = idx >> 4, ch = idx & 15;
                cp_async16(tb + (uint32_t)(r * BPITCH + ch * 16),
                           W + (size_t)(kt * 32 + r) * HCDIM + bn0 + ch * 8, 16);
            }
        }
        cp_commit();
    };

    load_tile(0, 0);
    load_tile(1, 1);

    for (int t = 0; t < KTILES; t++) {
        int b = t % NSTAGE;
        if (t + 2 < KTILES) { load_tile(t + 2, (t + 2) % NSTAGE); cp_wait2(); }
        else if (t + 1 < KTILES) cp_wait1();
        else cp_wait0();
        __syncthreads();

        uint32_t abase = sb + (uint32_t)b * BUF_B;
        uint32_t bbase = abase + 2 * A_TB;
#pragma unroll
        for (int ks = 0; ks < 2; ks++) {
            uint32_t ah[2][4], al[2][4];
#pragma unroll
            for (int im = 0; im < 2; im++) {
                uint32_t ra = abase
                    + (uint32_t)((wm * 32 + im * 16 + (lane & 15)) * APITCH
                                 + (ks * 16 + (lane >> 4) * 8) * 2);
                LDSM_X4(ah[im], ra);
                LDSM_X4(al[im], ra + A_TB);
            }
            int g = lane >> 3;
#pragma unroll
            for (int in2 = 0; in2 < 4; in2++) {
                uint32_t rb = bbase
                    + (uint32_t)((ks * 16 + (lane & 7) + (g & 1) * 8) * BPITCH
                                 + (wn * 64 + in2 * 16 + (g >> 1) * 8) * 2);
                uint32_t bh[4];
                LDSM_X4_TRANS(bh, rb);
#pragma unroll
                for (int im = 0; im < 2; im++) {
                    MMA_F16(acc[im][in2 * 2],     ah[im], (bh + 0));
                    MMA_F16(acc[im][in2 * 2],     al[im], (bh + 0));
                    MMA_F16(acc[im][in2 * 2 + 1], ah[im], (bh + 2));
                    MMA_F16(acc[im][in2 * 2 + 1], al[im], (bh + 2));
                }
            }
        }
        __syncthreads();
    }

    // ---- C store (fp16) ----
#pragma unroll
    for (int im = 0; im < 2; im++) {
        int r0 = bm0 + wm * 32 + im * 16 + (lane >> 2);
#pragma unroll
        for (int in_ = 0; in_ < 8; in_++) {
            int col = bn0 + wn * 64 + in_ * 8 + (lane & 3) * 2;
            if (r0 < M) {
                __half2 hp = __floats2half2_rn(acc[im][in_][0], acc[im][in_][1]);
                *(uint32_t*)&C[(size_t)r0 * HCDIM + col] = *(uint32_t*)&hp;
            }
            if (r0 + 8 < M) {
                __half2 hp = __floats2half2_rn(acc[im][in_][2], acc[im][in_][3]);
                *(uint32_t*)&C[(size_t)(r0 + 8) * HCDIM + col] = *(uint32_t*)&hp;
            }
        }
    }

    // ---- fused alpha: warp's 64 cols = one head ----
    {
        int hh = (bn0 >> 6) + wn;
        float pas[4] = {0.f, 0.f, 0.f, 0.f};
        float pad_[4] = {0.f, 0.f, 0.f, 0.f};
#pragma unroll
        for (int in_ = 0; in_ < 8; in_++) {
            int c0 = in_ * 8 + (lane & 3) * 2;
            float s0 = __ldg(&a_src[hh * CDIM + c0]);
            float s1 = __ldg(&a_src[hh * CDIM + c0 + 1]);
            float d0 = __ldg(&a_dst[hh * CDIM + c0]);
            float d1 = __ldg(&a_dst[hh * CDIM + c0 + 1]);
#pragma unroll
            for (int im = 0; im < 2; im++) {
                pas[im * 2]     += acc[im][in_][0] * s0 + acc[im][in_][1] * s1;
                pas[im * 2 + 1] += acc[im][in_][2] * s0 + acc[im][in_][3] * s1;
                pad_[im * 2]     += acc[im][in_][0] * d0 + acc[im][in_][1] * d1;
                pad_[im * 2 + 1] += acc[im][in_][2] * d0 + acc[im][in_][3] * d1;
            }
        }
#pragma unroll
        for (int k = 0; k < 4; k++) {
            pas[k]  += __shfl_xor_sync(0xffffffffu, pas[k], 1);
            pas[k]  += __shfl_xor_sync(0xffffffffu, pas[k], 2);
            pad_[k] += __shfl_xor_sync(0xffffffffu, pad_[k], 1);
            pad_[k] += __shfl_xor_sync(0xffffffffu, pad_[k], 2);
        }
        if ((lane & 3) == 0) {
#pragma unroll
            for (int im = 0; im < 2; im++) {
                int r0 = bm0 + wm * 32 + im * 16 + (lane >> 2);
                if (r0 < M) {
                    g_as[r0 * NHEADS + hh] = pas[im * 2];
                    g_ad[r0 * NHEADS + hh] = pad_[im * 2];
                }
                if (r0 + 8 < M) {
                    g_as[(r0 + 8) * NHEADS + hh] = pas[im * 2 + 1];
                    g_ad[(r0 + 8) * NHEADS + hh] = pad_[im * 2 + 1];
                }
            }
        }
    }
}

// ---------------- segment softmax: warp per node, 4 edges x 8 heads per iter ----------------
__global__ void stats_kernel() {
    int lane = threadIdx.x & 31;
    int n = (blockIdx.x * blockDim.x + threadIdx.x) >> 5;
    int hh = lane & 7, sub = lane >> 3;
    if (n >= N_NODES) return;
    int row = g_rowptr[n], end = g_rowptr[n + 1];
    float ad = g_ad[n * NHEADS + hh];
    float m = -1e30f, s = 0.f;
    for (int j = row + sub; j < end; j += 4) {
        int src = g_src_sorted[j];
        float e = g_as[src * NHEADS + hh] + ad;
        e = (e > 0.f) ? e : NEG_SLOPE * e;
        g_alpha[(size_t)j * NHEADS + hh] = e;
        float nm = fmaxf(m, e);
        s = s * __expf(m - nm) + __expf(e - nm);
        m = nm;
    }
#pragma unroll
    for (int off = 8; off <= 16; off <<= 1) {
        float mo = __shfl_xor_sync(0xffffffffu, m, off);
        float so = __shfl_xor_sync(0xffffffffu, s, off);
        float nm = fmaxf(m, mo);
        s = s * __expf(m - nm) + so * __expf(mo - nm);
        m = nm;
    }
    if (sub == 0) g_C[n * NHEADS + hh] = m + __logf(s + 1e-16f);
}

// ---------------- heavy aggregation (fp16 h, alpha inline; mode 1 fuses projection) -----
__global__ void __launch_bounds__(128) aggregate_kernel(const __half* __restrict__ hin,
                                                        const float* __restrict__ bias,
                                                        __half* __restrict__ xhi,
                                                        __half* __restrict__ xlo,
                                                        const float* __restrict__ Wout,
                                                        const float* __restrict__ bout,
                                                        float* __restrict__ outp,
                                                        int mode) {
    __shared__ float4 sm4[HCDIM / 4];
    __shared__ float x3row[CDIM];
    int n = blockIdx.x;
    int tid = threadIdx.x;
    int head = tid >> 4;
    int row = g_rowptr[n], end = g_rowptr[n + 1];
    float Cc = __ldg(&g_C[n * NHEADS + head]);
    const uint2* h2 = (const uint2*)hin;
    float4 acc = make_float4(0.f, 0.f, 0.f, 0.f);
    int j = row;
    for (; j + 3 < end; j += 4) {
        int s0 = __ldg(&g_src_sorted[j]);
        int s1 = __ldg(&g_src_sorted[j + 1]);
        int s2 = __ldg(&g_src_sorted[j + 2]);
        int s3 = __ldg(&g_src_sorted[j + 3]);
        float a0 = __expf(__ldg(&g_alpha[(size_t)j * NHEADS + head]) - Cc);
        float a1 = __expf(__ldg(&g_alpha[(size_t)(j + 1) * NHEADS + head]) - Cc);
        float a2 = __expf(__ldg(&g_alpha[(size_t)(j + 2) * NHEADS + head]) - Cc);
        float a3 = __expf(__ldg(&g_alpha[(size_t)(j + 3) * NHEADS + head]) - Cc);
        uint2 u0 = __ldg(&h2[(size_t)s0 * (HCDIM / 4) + tid]);
        uint2 u1 = __ldg(&h2[(size_t)s1 * (HCDIM / 4) + tid]);
        uint2 u2 = __ldg(&h2[(size_t)s2 * (HCDIM / 4) + tid]);
        uint2 u3 = __ldg(&h2[(size_t)s3 * (HCDIM / 4) + tid]);
        float2 f0a = __half22float2(*(__half2*)&u0.x), f0b = __half22float2(*(__half2*)&u0.y);
        float2 f1a = __half22float2(*(__half2*)&u1.x), f1b = __half22float2(*(__half2*)&u1.y);
        float2 f2a = __half22float2(*(__half2*)&u2.x), f2b = __half22float2(*(__half2*)&u2.y);
        float2 f3a = __half22float2(*(__half2*)&u3.x), f3b = __half22float2(*(__half2*)&u3.y);
        acc.x = fmaf(a0, f0a.x, fmaf(a1, f1a.x, fmaf(a2, f2a.x, fmaf(a3, f3a.x, acc.x))));
        acc.y = fmaf(a0, f0a.y, fmaf(a1, f1a.y, fmaf(a2, f2a.y, fmaf(a3, f3a.y, acc.y))));
        acc.z = fmaf(a0, f0b.x, fmaf(a1, f1b.x, fmaf(a2, f2b.x, fmaf(a3, f3b.x, acc.z))));
        acc.w = fmaf(a0, f0b.y, fmaf(a1, f1b.y, fmaf(a2, f2b.y, fmaf(a3, f3b.y, acc.w))));
    }
    for (; j < end; j++) {
        int s0 = __ldg(&g_src_sorted[j]);
        float a0 = __expf(__ldg(&g_alpha[(size_t)j * NHEADS + head]) - Cc);
        uint2 u0 = __ldg(&h2[(size_t)s0 * (HCDIM / 4) + tid]);
        float2 f0a = __half22float2(*(__half2*)&u0.x);
        float2 f0b = __half22float2(*(__half2*)&u0.y);
        acc.x = fmaf(a0, f0a.x, acc.x);
        acc.y = fmaf(a0, f0a.y, acc.y);
        acc.z = fmaf(a0, f0b.x, acc.z);
        acc.w = fmaf(a0, f0b.y, acc.w);
    }
    if (mode == 0) {
        float4 b4 = ((const float4*)bias)[tid];
        float v[4];
        v[0] = acc.x + b4.x; v[0] = (v[0] > 0.f) ? v[0] : expm1f(v[0]);
        v[1] = acc.y + b4.y; v[1] = (v[1] > 0.f) ? v[1] : expm1f(v[1]);
        v[2] = acc.z + b4.z; v[2] = (v[2] > 0.f) ? v[2] : expm1f(v[2]);
        v[3] = acc.w + b4.w; v[3] = (v[3] > 0.f) ? v[3] : expm1f(v[3]);
        __half hi[4], lo[4];
#pragma unroll
        for (int q = 0; q < 4; q++) {
            hi[q] = __float2half_rn(v[q]);
            lo[q] = __float2half_rn(v[q] - __half2float(hi[q]));
        }
        size_t base = ((size_t)n * HCDIM + tid * 4) >> 1;   // uint32 index
        uint32_t* hip = (uint32_t*)xhi;
        uint32_t* lop = (uint32_t*)xlo;
        __half2 h01 = __halves2half2(hi[0], hi[1]);
        __half2 h23 = __halves2half2(hi[2], hi[3]);
        __half2 l01 = __halves2half2(lo[0], lo[1]);
        __half2 l23 = __halves2half2(lo[2], lo[3]);
        hip[base]     = *(uint32_t*)&h01;
        hip[base + 1] = *(uint32_t*)&h23;
        lop[base]     = *(uint32_t*)&l01;
        lop[base + 1] = *(uint32_t*)&l23;
    } else {
        sm4[tid] = acc;
        __syncthreads();
        if (tid < 16) {
            float4 s = make_float4(0.f, 0.f, 0.f, 0.f);
#pragma unroll
            for (int hh = 0; hh < NHEADS; hh++) {
                float4 f = sm4[hh * 16 + tid];
                s.x += f.x; s.y += f.y; s.z += f.z; s.w += f.w;
            }
            float4 b4 = ((const float4*)bias)[tid];
            x3row[tid * 4 + 0] = s.x * (1.0f / NHEADS) + b4.x;
            x3row[tid * 4 + 1] = s.y * (1.0f / NHEADS) + b4.y;
            x3row[tid * 4 + 2] = s.z * (1.0f / NHEADS) + b4.z;
            x3row[tid * 4 + 3] = s.w * (1.0f / NHEADS) + b4.w;
        }
        __syncthreads();
        int o = tid >> 3, c8 = tid & 7;
        float accp = 0.f;
        if (o < OUT_DIM) {
#pragma unroll
            for (int c = 0; c < 8; c++) {
                int cc = c8 * 8 + c;
                accp = fmaf(x3row[cc], __ldg(&Wout[cc * OUT_DIM + o]), accp);
            }
        }
        accp += __shfl_xor_sync(0xffffffffu, accp, 1);
        accp += __shfl_xor_sync(0xffffffffu, accp, 2);
        accp += __shfl_xor_sync(0xffffffffu, accp, 4);
        if (c8 == 0 && o < OUT_DIM)
            outp[(size_t)n * OUT_DIM + o] = accp + __ldg(&bout[o]);
    }
}

// ---------------- launch ----------------
extern "C" void kernel_launch(void* const* d_in, const int* in_sizes, int n_in,
                              void* d_out, int out_size) {
    const float* x    = (const float*)d_in[0];
    const int*   ei   = (const int*)d_in[1];
    const float* W1   = (const float*)d_in[2];
    const float* a1s  = (const float*)d_in[3];
    const float* a1d  = (const float*)d_in[4];
    const float* b1   = (const float*)d_in[5];
    const float* W2   = (const float*)d_in[6];
    const float* a2s  = (const float*)d_in[7];
    const float* a2d  = (const float*)d_in[8];
    const float* b2   = (const float*)d_in[9];
    const float* W3   = (const float*)d_in[10];
    const float* a3s  = (const float*)d_in[11];
    const float* a3d  = (const float*)d_in[12];
    const float* b3   = (const float*)d_in[13];
    const float* Wout = (const float*)d_in[14];
    const float* bout = (const float*)d_in[15];
    float* out = (float*)d_out;

    __half *p_h, *p_xhi, *p_xlo, *p_w2, *p_w3;
    cudaGetSymbolAddress((void**)&p_h,   g_h);
    cudaGetSymbolAddress((void**)&p_xhi, g_xhi);
    cudaGetSymbolAddress((void**)&p_xlo, g_xlo);
    cudaGetSymbolAddress((void**)&p_w2,  g_w2);
    cudaGetSymbolAddress((void**)&p_w3,  g_w3);

    cudaFuncSetAttribute(mma_gemm_kernel, cudaFuncAttributeMaxDynamicSharedMemorySize, GSMEM);

    const int scan_blocks = (N_NODES + 1023) / 1024;

    init_detect_kernel<<<(N_NODES + 255) / 256, 256>>>(ei);
    count_kernel<<<(NE + 255) / 256, 256>>>(ei);
    scan_block_kernel<<<scan_blocks, 1024>>>();
    scan_add_kernel<<<scan_blocks, 1024>>>();
    fill_kernel<<<(E_TOT + 255) / 256, 256>>>(ei);

    int wconv_blocks = (2 * HCDIM * HCDIM + 255) / 256;
    wconv_kernel<<<wconv_blocks, 256>>>(W2, W3, p_w2, p_w3);

    dim3 sgrid(HCDIM / BN, (N_NODES + BM - 1) / BM);
    dim3 mgrid(HCDIM / 128, (N_NODES + 127) / 128);
    int stats_blocks = (N_NODES * 32 + 255) / 256;   // warp per node

    // ---- layer 1 ----
    gemm_small_kernel<<<sgrid, 256>>>(x, W1, a1s, a1d, p_h, N_NODES, F_IN, HCDIM);
    stats_kernel<<<stats_blocks, 256>>>();
    aggregate_kernel<<<N_NODES, 128>>>(p_h, b1, p_xhi, p_xlo, nullptr, nullptr, nullptr, 0);

    // ---- layer 2 ----
    mma_gemm_kernel<<<mgrid, 256, GSMEM>>>(p_xhi, p_xlo, p_w2, a2s, a2d, p_h, N_NODES);
    stats_kernel<<<stats_blocks, 256>>>();
    aggregate_kernel<<<N_NODES, 128>>>(p_h, b2, p_xhi, p_xlo, nullptr, nullptr, nullptr, 0);

    // ---- layer 3 (aggregate + mean + bias + projection fused) ----
    mma_gemm_kernel<<<mgrid, 256, GSMEM>>>(p_xhi, p_xlo, p_w3, a3s, a3d, p_h, N_NODES);
    stats_kernel<<<stats_blocks, 256>>>();
    aggregate_kernel<<<N_NODES, 128>>>(p_h, b3, nullptr, nullptr, Wout, bout, out, 1);
}

// round 17
// speedup vs baseline: 1.2381x; 1.0132x over previous
#include <cuda_runtime.h>
#include <cuda_bf16.h>
#include <cuda_fp16.h>
#include <cstdint>
#include <stdint.h>
#include <math.h>

#define N_NODES 50000
#define F_IN    18
#define NHEADS  8
#define CDIM    64
#define HCDIM   512
#define NE      400000
#define E_TOT   (NE + N_NODES)
#define OUT_DIM 15
#define NEG_SLOPE 0.2f

// ---------------- scratch (static device globals; no runtime allocation) ----------------
__device__ __half g_h [N_NODES * HCDIM];          // post-GEMM features (fp16)
__device__ __half g_xhi[N_NODES * HCDIM];         // activation hi (fp16)
__device__ __half g_xlo[N_NODES * HCDIM];         // activation lo (fp16 residual)
__device__ __half g_w2[HCDIM * HCDIM];            // W2 fp16
__device__ __half g_w3[HCDIM * HCDIM];
__device__ float g_as[N_NODES * NHEADS];
__device__ float g_ad[N_NODES * NHEADS];
__device__ float g_C [N_NODES * NHEADS];          // softmax constant: m + log(s+eps)
__device__ float g_alpha[(size_t)E_TOT * NHEADS]; // raw e (LeakyReLU'd logits)
__device__ int   g_src_sorted[E_TOT];
__device__ int   g_rowptr[N_NODES + 1];
__device__ int   g_cursor[N_NODES];
__device__ int   g_counts[N_NODES];
__device__ int   g_part[64];
__device__ int   g_is64;

// ---------------- PTX helpers (portable: sm_80-era features only) ----------------
__device__ __forceinline__ uint32_t smem_u32(const void* p) {
    uint32_t a;
    asm("{ .reg .u64 t; cvta.to.shared.u64 t, %1; cvt.u32.u64 %0, t; }" : "=r"(a) : "l"(p));
    return a;
}
static __device__ __forceinline__ void cp_async16(uint32_t dst, const void* src, int sz) {
    asm volatile("cp.async.cg.shared.global [%0], [%1], 16, %2;\n"
                 :: "r"(dst), "l"(src), "r"(sz) : "memory");
}
static __device__ __forceinline__ void cp_commit() {
    asm volatile("cp.async.commit_group;" ::: "memory");
}
static __device__ __forceinline__ void cp_wait0() {
    asm volatile("cp.async.wait_group 0;" ::: "memory");
}
static __device__ __forceinline__ void cp_wait1() {
    asm volatile("cp.async.wait_group 1;" ::: "memory");
}
static __device__ __forceinline__ void cp_wait2() {
    asm volatile("cp.async.wait_group 2;" ::: "memory");
}

#define LDSM_X4(r, addr) \
    asm volatile("ldmatrix.sync.aligned.m8n8.x4.shared.b16 {%0,%1,%2,%3}, [%4];" \
        : "=r"((r)[0]), "=r"((r)[1]), "=r"((r)[2]), "=r"((r)[3]) : "r"(addr))
#define LDSM_X4_TRANS(r, addr) \
    asm volatile("ldmatrix.sync.aligned.m8n8.x4.trans.shared.b16 {%0,%1,%2,%3}, [%4];" \
        : "=r"((r)[0]), "=r"((r)[1]), "=r"((r)[2]), "=r"((r)[3]) : "r"(addr))
#define MMA_F16(c, a, b) \
    asm volatile("mma.sync.aligned.m16n8k16.row.col.f32.f16.f16.f32 " \
        "{%0,%1,%2,%3},{%4,%5,%6,%7},{%8,%9},{%0,%1,%2,%3};" \
        : "+f"((c)[0]), "+f"((c)[1]), "+f"((c)[2]), "+f"((c)[3]) \
        : "r"((a)[0]), "r"((a)[1]), "r"((a)[2]), "r"((a)[3]), "r"((b)[0]), "r"((b)[1]))

// ---------------- edge dtype handling ----------------
__device__ __forceinline__ int edge_at(const int* p, int idx) {
    return g_is64 ? p[2 * idx] : p[idx];
}

// ---------------- CSR build (5 kernels) ----------------
__global__ void init_detect_kernel(const int* __restrict__ p) {
    int i = blockIdx.x * blockDim.x + threadIdx.x;
    if (i < N_NODES) g_counts[i] = 1;
    if (blockIdx.x == 0) {
        __shared__ int red[256];
        int acc = 0;
        for (int k = threadIdx.x; k < 8192; k += 256) acc |= p[2 * k + 1];
        red[threadIdx.x] = acc;
        __syncthreads();
        for (int s = 128; s > 0; s >>= 1) {
            if (threadIdx.x < s) red[threadIdx.x] |= red[threadIdx.x + s];
            __syncthreads();
        }
        if (threadIdx.x == 0) g_is64 = (red[0] == 0) ? 1 : 0;
    }
}
__global__ void count_kernel(const int* __restrict__ ei) {
    int i = blockIdx.x * blockDim.x + threadIdx.x;
    if (i < NE) atomicAdd(&g_counts[edge_at(ei, NE + i)], 1);
}
__global__ void __launch_bounds__(1024) scan_block_kernel() {
    __shared__ int sm[1024];
    int i = blockIdx.x * 1024 + threadIdx.x;
    int v = (i < N_NODES) ? g_counts[i] : 0;
    sm[threadIdx.x] = v;
    __syncthreads();
    for (int off = 1; off < 1024; off <<= 1) {
        int t = (threadIdx.x >= off) ? sm[threadIdx.x - off] : 0;
        __syncthreads();
        sm[threadIdx.x] += t;
        __syncthreads();
    }
    if (i < N_NODES) g_rowptr[i] = sm[threadIdx.x] - v;
    if (threadIdx.x == 1023) g_part[blockIdx.x] = sm[1023];
}
__global__ void __launch_bounds__(1024) scan_add_kernel() {
    __shared__ int base_s;
    if (threadIdx.x == 0) {
        int run = 0;
        for (int b = 0; b < (int)blockIdx.x; b++) run += g_part[b];
        base_s = run;
    }
    __syncthreads();
    int i = blockIdx.x * 1024 + threadIdx.x;
    if (i < N_NODES) {
        int v = g_rowptr[i] + base_s;
        g_rowptr[i] = v;
        g_cursor[i] = v;
    }
    if (i == 0) g_rowptr[N_NODES] = E_TOT;
}
__global__ void fill_kernel(const int* __restrict__ ei) {
    int i = blockIdx.x * blockDim.x + threadIdx.x;
    if (i >= E_TOT) return;
    int src, dst;
    if (i < NE) { src = edge_at(ei, i); dst = edge_at(ei, NE + i); }
    else        { src = dst = i - NE; }
    int pos = atomicAdd(&g_cursor[dst], 1);
    g_src_sorted[pos] = src;
}

// ---------------- small-K GEMM (layer 1, K=18) with fused alpha epilogue ----------------
#define BM 128
#define BN 64
#define BK 16

__global__ void __launch_bounds__(256) gemm_small_kernel(const float* __restrict__ A,
                                                         const float* __restrict__ B,
                                                         const float* __restrict__ a_src,
                                                         const float* __restrict__ a_dst,
                                                         __half* __restrict__ C,
                                                         int M, int K, int Nc) {
    __shared__ float As[BK][BM + 4];
    __shared__ float Bs[BK][BN + 4];
    int tid = threadIdx.x;
    int bn0 = blockIdx.x * BN;
    int bm0 = blockIdx.y * BM;
    int tr = tid >> 4;
    int tc = tid & 15;
    int a_row = tid >> 1;
    int a_cb  = (tid & 1) * 8;
    int b_row = tid >> 4;
    int b_col = (tid & 15) * 4;

    float acc[8][4];
#pragma unroll
    for (int i = 0; i < 8; i++)
#pragma unroll
        for (int j = 0; j < 4; j++) acc[i][j] = 0.f;

    for (int k0 = 0; k0 < K; k0 += BK) {
        int gm = bm0 + a_row;
#pragma unroll
        for (int i = 0; i < 8; i++) {
            int gk = k0 + a_cb + i;
            As[a_cb + i][a_row] = (gm < M && gk < K) ? A[(long long)gm * K + gk] : 0.f;
        }
        {
            int gk = k0 + b_row;
            float4 bv = make_float4(0.f, 0.f, 0.f, 0.f);
            if (gk < K) bv = *(const float4*)&B[(long long)gk * Nc + bn0 + b_col];
            *(float4*)&Bs[b_row][b_col] = bv;
        }
        __syncthreads();
#pragma unroll
        for (int kk = 0; kk < BK; kk++) {
            float a[8], b[4];
#pragma unroll
            for (int i = 0; i < 8; i++) a[i] = As[kk][tr * 8 + i];
#pragma unroll
            for (int j = 0; j < 4; j++) b[j] = Bs[kk][tc * 4 + j];
#pragma unroll
            for (int i = 0; i < 8; i++)
#pragma unroll
                for (int j = 0; j < 4; j++) acc[i][j] += a[i] * b[j];
        }
        __syncthreads();
    }
#pragma unroll
    for (int i = 0; i < 8; i++) {
        int gm = bm0 + tr * 8 + i;
        if (gm < M) {
            __half2 h01 = __floats2half2_rn(acc[i][0], acc[i][1]);
            __half2 h23 = __floats2half2_rn(acc[i][2], acc[i][3]);
            uint2 u;
            u.x = *(uint32_t*)&h01;
            u.y = *(uint32_t*)&h23;
            *(uint2*)&C[(size_t)gm * Nc + bn0 + tc * 4] = u;
        }
    }

    // fused alpha for this head
    {
        int hh = blockIdx.x;
        float pas[8], pad_[8];
#pragma unroll
        for (int i = 0; i < 8; i++) { pas[i] = 0.f; pad_[i] = 0.f; }
#pragma unroll
        for (int j = 0; j < 4; j++) {
            float sj = __ldg(&a_src[hh * CDIM + tc * 4 + j]);
            float dj = __ldg(&a_dst[hh * CDIM + tc * 4 + j]);
#pragma unroll
            for (int i = 0; i < 8; i++) {
                pas[i]  = fmaf(acc[i][j], sj, pas[i]);
                pad_[i] = fmaf(acc[i][j], dj, pad_[i]);
            }
        }
#pragma unroll
        for (int off = 1; off < 16; off <<= 1) {
#pragma unroll
            for (int i = 0; i < 8; i++) {
                pas[i]  += __shfl_xor_sync(0xffffffffu, pas[i], off);
                pad_[i] += __shfl_xor_sync(0xffffffffu, pad_[i], off);
            }
        }
        if (tc == 0) {
#pragma unroll
            for (int i = 0; i < 8; i++) {
                int gm = bm0 + tr * 8 + i;
                if (gm < M) {
                    g_as[gm * NHEADS + hh] = pas[i];
                    g_ad[gm * NHEADS + hh] = pad_[i];
                }
            }
        }
    }
}

// ---------------- W fp16 convert (W2 and W3 in one launch) ----------------
__global__ void __launch_bounds__(256) wconv_kernel(const float* __restrict__ W2,
                                                    const float* __restrict__ W3,
                                                    __half* __restrict__ w2,
                                                    __half* __restrict__ w3) {
    int i = blockIdx.x * blockDim.x + threadIdx.x;
    const int NW = HCDIM * HCDIM;
    if (i < NW)           w2[i]      = __float2half_rn(W2[i]);
    else if (i < 2 * NW)  w3[i - NW] = __float2half_rn(W3[i - NW]);
}

// ---------------- persistent mma.sync fp16 2-product GEMM + fused alpha epilogue --------
#define KTILES  (HCDIM / 32)      // 16
#define APITCH  80
#define BPITCH  272
#define A_TB    (128 * APITCH)    // 10240
#define B_TB    (32 * BPITCH)     // 8704
#define BUF_B   (2 * A_TB + B_TB) // 29184 (Ahi + Alo + W)
#define NSTAGE  3
#define GSMEM   (NSTAGE * BUF_B)  // 87552; 2 CTAs/SM
#define NTILE_N (HCDIM / 128)     // 4
#define NTILE_M ((N_NODES + 127) / 128)   // 391
#define NTILES  (NTILE_N * NTILE_M)       // 1564
#define NBLK    296               // 148 SMs x 2 resident

__global__ void __launch_bounds__(256, 2)
mma_gemm_kernel(const __half* __restrict__ Ahi,
                const __half* __restrict__ Alo,
                const __half* __restrict__ W,
                const float* __restrict__ a_src,
                const float* __restrict__ a_dst,
                __half* __restrict__ C, int M) {
    extern __shared__ char smem[];
    uint32_t sb = smem_u32(smem);
    int tid = threadIdx.x, lane = tid & 31, wid = tid >> 5;
    int wm = wid & 3, wn = wid >> 2;

    for (int tt = blockIdx.x; tt < NTILES; tt += NBLK) {
        int bm0 = (tt >> 2) * 128;
        int bn0 = (tt & 3) * 128;

        float acc[2][8][4];
#pragma unroll
        for (int im = 0; im < 2; im++)
#pragma unroll
            for (int in_ = 0; in_ < 8; in_++)
#pragma unroll
                for (int q = 0; q < 4; q++) acc[im][in_][q] = 0.f;

        auto load_tile = [&](int kt, int b) {
            uint32_t base = sb + (uint32_t)b * BUF_B;
#pragma unroll
            for (int m = 0; m < 2; m++) {
                const __half* srcm = m ? Alo : Ahi;
                uint32_t tb = base + (uint32_t)m * A_TB;
#pragma unroll
                for (int q = 0; q < 2; q++) {
                    int idx = q * 256 + tid;
                    int r = idx >> 2, ch = idx & 3;
                    int gr = bm0 + r;
                    int sz = 16;
                    if (gr >= M) { gr = 0; sz = 0; }
                    cp_async16(tb + (uint32_t)(r * APITCH + ch * 16),
                               srcm + (size_t)gr * HCDIM + kt * 32 + ch * 8, sz);
                }
            }
            {
                uint32_t tb = base + 2 * A_TB;
#pragma unroll
                for (int q = 0; q < 2; q++) {
                    int idx = q * 256 + tid;
                    int r = idx >> 4, ch = idx & 15;
                    cp_async16(tb + (uint32_t)(r * BPITCH + ch * 16),
                               W + (size_t)(kt * 32 + r) * HCDIM + bn0 + ch * 8, 16);
                }
            }
            cp_commit();
        };

        load_tile(0, 0);
        load_tile(1, 1);

        for (int t = 0; t < KTILES; t++) {
            int b = t % NSTAGE;
            if (t + 2 < KTILES) { load_tile(t + 2, (t + 2) % NSTAGE); cp_wait2(); }
            else if (t + 1 < KTILES) cp_wait1();
            else cp_wait0();
            __syncthreads();

            uint32_t abase = sb + (uint32_t)b * BUF_B;
            uint32_t bbase = abase + 2 * A_TB;
#pragma unroll
            for (int ks = 0; ks < 2; ks++) {
                uint32_t ah[2][4], al[2][4];
#pragma unroll
                for (int im = 0; im < 2; im++) {
                    uint32_t ra = abase
                        + (uint32_t)((wm * 32 + im * 16 + (lane & 15)) * APITCH
                                     + (ks * 16 + (lane >> 4) * 8) * 2);
                    LDSM_X4(ah[im], ra);
                    LDSM_X4(al[im], ra + A_TB);
                }
                int g = lane >> 3;
#pragma unroll
                for (int in2 = 0; in2 < 4; in2++) {
                    uint32_t rb = bbase
                        + (uint32_t)((ks * 16 + (lane & 7) + (g & 1) * 8) * BPITCH
                                     + (wn * 64 + in2 * 16 + (g >> 1) * 8) * 2);
                    uint32_t bh[4];
                    LDSM_X4_TRANS(bh, rb);
#pragma unroll
                    for (int im = 0; im < 2; im++) {
                        MMA_F16(acc[im][in2 * 2],     ah[im], (bh + 0));
                        MMA_F16(acc[im][in2 * 2],     al[im], (bh + 0));
                        MMA_F16(acc[im][in2 * 2 + 1], ah[im], (bh + 2));
                        MMA_F16(acc[im][in2 * 2 + 1], al[im], (bh + 2));
                    }
                }
            }
            __syncthreads();
        }

        // ---- C store (fp16) ----
#pragma unroll
        for (int im = 0; im < 2; im++) {
            int r0 = bm0 + wm * 32 + im * 16 + (lane >> 2);
#pragma unroll
            for (int in_ = 0; in_ < 8; in_++) {
                int col = bn0 + wn * 64 + in_ * 8 + (lane & 3) * 2;
                if (r0 < M) {
                    __half2 hp = __floats2half2_rn(acc[im][in_][0], acc[im][in_][1]);
                    *(uint32_t*)&C[(size_t)r0 * HCDIM + col] = *(uint32_t*)&hp;
                }
                if (r0 + 8 < M) {
                    __half2 hp = __floats2half2_rn(acc[im][in_][2], acc[im][in_][3]);
                    *(uint32_t*)&C[(size_t)(r0 + 8) * HCDIM + col] = *(uint32_t*)&hp;
                }
            }
        }

        // ---- fused alpha: warp's 64 cols = one head ----
        {
            int hh = (bn0 >> 6) + wn;
            float pas[4] = {0.f, 0.f, 0.f, 0.f};
            float pad_[4] = {0.f, 0.f, 0.f, 0.f};
#pragma unroll
            for (int in_ = 0; in_ < 8; in_++) {
                int c0 = in_ * 8 + (lane & 3) * 2;
                float s0 = __ldg(&a_src[hh * CDIM + c0]);
                float s1 = __ldg(&a_src[hh * CDIM + c0 + 1]);
                float d0 = __ldg(&a_dst[hh * CDIM + c0]);
                float d1 = __ldg(&a_dst[hh * CDIM + c0 + 1]);
#pragma unroll
                for (int im = 0; im < 2; im++) {
                    pas[im * 2]     += acc[im][in_][0] * s0 + acc[im][in_][1] * s1;
                    pas[im * 2 + 1] += acc[im][in_][2] * s0 + acc[im][in_][3] * s1;
                    pad_[im * 2]     += acc[im][in_][0] * d0 + acc[im][in_][1] * d1;
                    pad_[im * 2 + 1] += acc[im][in_][2] * d0 + acc[im][in_][3] * d1;
                }
            }
#pragma unroll
            for (int k = 0; k < 4; k++) {
                pas[k]  += __shfl_xor_sync(0xffffffffu, pas[k], 1);
                pas[k]  += __shfl_xor_sync(0xffffffffu, pas[k], 2);
                pad_[k] += __shfl_xor_sync(0xffffffffu, pad_[k], 1);
                pad_[k] += __shfl_xor_sync(0xffffffffu, pad_[k], 2);
            }
            if ((lane & 3) == 0) {
#pragma unroll
                for (int im = 0; im < 2; im++) {
                    int r0 = bm0 + wm * 32 + im * 16 + (lane >> 2);
                    if (r0 < M) {
                        g_as[r0 * NHEADS + hh] = pas[im * 2];
                        g_ad[r0 * NHEADS + hh] = pad_[im * 2];
                    }
                    if (r0 + 8 < M) {
                        g_as[(r0 + 8) * NHEADS + hh] = pas[im * 2 + 1];
                        g_ad[(r0 + 8) * NHEADS + hh] = pad_[im * 2 + 1];
                    }
                }
            }
        }
        __syncthreads();   // all smem reads done before next tile's prologue overwrites
    }
}

// ---------------- segment softmax: warp per node, 4 edges x 8 heads per iter ----------------
__global__ void stats_kernel() {
    int lane = threadIdx.x & 31;
    int n = (blockIdx.x * blockDim.x + threadIdx.x) >> 5;
    int hh = lane & 7, sub = lane >> 3;
    if (n >= N_NODES) return;
    int row = g_rowptr[n], end = g_rowptr[n + 1];
    float ad = g_ad[n * NHEADS + hh];
    float m = -1e30f, s = 0.f;
    for (int j = row + sub; j < end; j += 4) {
        int src = g_src_sorted[j];
        float e = g_as[src * NHEADS + hh] + ad;
        e = (e > 0.f) ? e : NEG_SLOPE * e;
        g_alpha[(size_t)j * NHEADS + hh] = e;
        float nm = fmaxf(m, e);
        s = s * __expf(m - nm) + __expf(e - nm);
        m = nm;
    }
#pragma unroll
    for (int off = 8; off <= 16; off <<= 1) {
        float mo = __shfl_xor_sync(0xffffffffu, m, off);
        float so = __shfl_xor_sync(0xffffffffu, s, off);
        float nm = fmaxf(m, mo);
        s = s * __expf(m - nm) + so * __expf(mo - nm);
        m = nm;
    }
    if (sub == 0) g_C[n * NHEADS + hh] = m + __logf(s + 1e-16f);
}

// ---------------- heavy aggregation (fp16 h, alpha inline; mode 1 fuses projection) -----
__global__ void __launch_bounds__(128) aggregate_kernel(const __half* __restrict__ hin,
                                                        const float* __restrict__ bias,
                                                        __half* __restrict__ xhi,
                                                        __half* __restrict__ xlo,
                                                        const float* __restrict__ Wout,
                                                        const float* __restrict__ bout,
                                                        float* __restrict__ outp,
                                                        int mode) {
    __shared__ float4 sm4[HCDIM / 4];
    __shared__ float x3row[CDIM];
    int n = blockIdx.x;
    int tid = threadIdx.x;
    int head = tid >> 4;
    int row = g_rowptr[n], end = g_rowptr[n + 1];
    float Cc = __ldg(&g_C[n * NHEADS + head]);
    const uint2* h2 = (const uint2*)hin;
    float4 acc = make_float4(0.f, 0.f, 0.f, 0.f);
    int j = row;
    for (; j + 3 < end; j += 4) {
        int s0 = __ldg(&g_src_sorted[j]);
        int s1 = __ldg(&g_src_sorted[j + 1]);
        int s2 = __ldg(&g_src_sorted[j + 2]);
        int s3 = __ldg(&g_src_sorted[j + 3]);
        float a0 = __expf(__ldg(&g_alpha[(size_t)j * NHEADS + head]) - Cc);
        float a1 = __expf(__ldg(&g_alpha[(size_t)(j + 1) * NHEADS + head]) - Cc);
        float a2 = __expf(__ldg(&g_alpha[(size_t)(j + 2) * NHEADS + head]) - Cc);
        float a3 = __expf(__ldg(&g_alpha[(size_t)(j + 3) * NHEADS + head]) - Cc);
        uint2 u0 = __ldg(&h2[(size_t)s0 * (HCDIM / 4) + tid]);
        uint2 u1 = __ldg(&h2[(size_t)s1 * (HCDIM / 4) + tid]);
        uint2 u2 = __ldg(&h2[(size_t)s2 * (HCDIM / 4) + tid]);
        uint2 u3 = __ldg(&h2[(size_t)s3 * (HCDIM / 4) + tid]);
        float2 f0a = __half22float2(*(__half2*)&u0.x), f0b = __half22float2(*(__half2*)&u0.y);
        float2 f1a = __half22float2(*(__half2*)&u1.x), f1b = __half22float2(*(__half2*)&u1.y);
        float2 f2a = __half22float2(*(__half2*)&u2.x), f2b = __half22float2(*(__half2*)&u2.y);
        float2 f3a = __half22float2(*(__half2*)&u3.x), f3b = __half22float2(*(__half2*)&u3.y);
        acc.x = fmaf(a0, f0a.x, fmaf(a1, f1a.x, fmaf(a2, f2a.x, fmaf(a3, f3a.x, acc.x))));
        acc.y = fmaf(a0, f0a.y, fmaf(a1, f1a.y, fmaf(a2, f2a.y, fmaf(a3, f3a.y, acc.y))));
        acc.z = fmaf(a0, f0b.x, fmaf(a1, f1b.x, fmaf(a2, f2b.x, fmaf(a3, f3b.x, acc.z))));
        acc.w = fmaf(a0, f0b.y, fmaf(a1, f1b.y, fmaf(a2, f2b.y, fmaf(a3, f3b.y, acc.w))));
    }
    for (; j < end; j++) {
        int s0 = __ldg(&g_src_sorted[j]);
        float a0 = __expf(__ldg(&g_alpha[(size_t)j * NHEADS + head]) - Cc);
        uint2 u0 = __ldg(&h2[(size_t)s0 * (HCDIM / 4) + tid]);
        float2 f0a = __half22float2(*(__half2*)&u0.x);
        float2 f0b = __half22float2(*(__half2*)&u0.y);
        acc.x = fmaf(a0, f0a.x, acc.x);
        acc.y = fmaf(a0, f0a.y, acc.y);
        acc.z = fmaf(a0, f0b.x, acc.z);
        acc.w = fmaf(a0, f0b.y, acc.w);
    }
    if (mode == 0) {
        float4 b4 = ((const float4*)bias)[tid];
        float v[4];
        v[0] = acc.x + b4.x; v[0] = (v[0] > 0.f) ? v[0] : expm1f(v[0]);
        v[1] = acc.y + b4.y; v[1] = (v[1] > 0.f) ? v[1] : expm1f(v[1]);
        v[2] = acc.z + b4.z; v[2] = (v[2] > 0.f) ? v[2] : expm1f(v[2]);
        v[3] = acc.w + b4.w; v[3] = (v[3] > 0.f) ? v[3] : expm1f(v[3]);
        __half hi[4], lo[4];
#pragma unroll
        for (int q = 0; q < 4; q++) {
            hi[q] = __float2half_rn(v[q]);
            lo[q] = __float2half_rn(v[q] - __half2float(hi[q]));
        }
        size_t base = ((size_t)n * HCDIM + tid * 4) >> 1;
        uint32_t* hip = (uint32_t*)xhi;
        uint32_t* lop = (uint32_t*)xlo;
        __half2 h01 = __halves2half2(hi[0], hi[1]);
        __half2 h23 = __halves2half2(hi[2], hi[3]);
        __half2 l01 = __halves2half2(lo[0], lo[1]);
        __half2 l23 = __halves2half2(lo[2], lo[3]);
        hip[base]     = *(uint32_t*)&h01;
        hip[base + 1] = *(uint32_t*)&h23;
        lop[base]     = *(uint32_t*)&l01;
        lop[base + 1] = *(uint32_t*)&l23;
    } else {
        sm4[tid] = acc;
        __syncthreads();
        if (tid < 16) {
            float4 s = make_float4(0.f, 0.f, 0.f, 0.f);
#pragma unroll
            for (int hh = 0; hh < NHEADS; hh++) {
                float4 f = sm4[hh * 16 + tid];
                s.x += f.x; s.y += f.y; s.z += f.z; s.w += f.w;
            }
            float4 b4 = ((const float4*)bias)[tid];
            x3row[tid * 4 + 0] = s.x * (1.0f / NHEADS) + b4.x;
            x3row[tid * 4 + 1] = s.y * (1.0f / NHEADS) + b4.y;
            x3row[tid * 4 + 2] = s.z * (1.0f / NHEADS) + b4.z;
            x3row[tid * 4 + 3] = s.w * (1.0f / NHEADS) + b4.w;
        }
        __syncthreads();
        int o = tid >> 3, c8 = tid & 7;
        float accp = 0.f;
        if (o < OUT_DIM) {
#pragma unroll
            for (int c = 0; c < 8; c++) {
                int cc = c8 * 8 + c;
                accp = fmaf(x3row[cc], __ldg(&Wout[cc * OUT_DIM + o]), accp);
            }
        }
        accp += __shfl_xor_sync(0xffffffffu, accp, 1);
        accp += __shfl_xor_sync(0xffffffffu, accp, 2);
        accp += __shfl_xor_sync(0xffffffffu, accp, 4);
        if (c8 == 0 && o < OUT_DIM)
            outp[(size_t)n * OUT_DIM + o] = accp + __ldg(&bout[o]);
    }
}

// ---------------- launch ----------------
extern "C" void kernel_launch(void* const* d_in, const int* in_sizes, int n_in,
                              void* d_out, int out_size) {
    const float* x    = (const float*)d_in[0];
    const int*   ei   = (const int*)d_in[1];
    const float* W1   = (const float*)d_in[2];
    const float* a1s  = (const float*)d_in[3];
    const float* a1d  = (const float*)d_in[4];
    const float* b1   = (const float*)d_in[5];
    const float* W2   = (const float*)d_in[6];
    const float* a2s  = (const float*)d_in[7];
    const float* a2d  = (const float*)d_in[8];
    const float* b2   = (const float*)d_in[9];
    const float* W3   = (const float*)d_in[10];
    const float* a3s  = (const float*)d_in[11];
    const float* a3d  = (const float*)d_in[12];
    const float* b3   = (const float*)d_in[13];
    const float* Wout = (const float*)d_in[14];
    const float* bout = (const float*)d_in[15];
    float* out = (float*)d_out;

    __half *p_h, *p_xhi, *p_xlo, *p_w2, *p_w3;
    cudaGetSymbolAddress((void**)&p_h,   g_h);
    cudaGetSymbolAddress((void**)&p_xhi, g_xhi);
    cudaGetSymbolAddress((void**)&p_xlo, g_xlo);
    cudaGetSymbolAddress((void**)&p_w2,  g_w2);
    cudaGetSymbolAddress((void**)&p_w3,  g_w3);

    cudaFuncSetAttribute(mma_gemm_kernel, cudaFuncAttributeMaxDynamicSharedMemorySize, GSMEM);

    const int scan_blocks = (N_NODES + 1023) / 1024;

    init_detect_kernel<<<(N_NODES + 255) / 256, 256>>>(ei);
    count_kernel<<<(NE + 255) / 256, 256>>>(ei);
    scan_block_kernel<<<scan_blocks, 1024>>>();
    scan_add_kernel<<<scan_blocks, 1024>>>();
    fill_kernel<<<(E_TOT + 255) / 256, 256>>>(ei);

    int wconv_blocks = (2 * HCDIM * HCDIM + 255) / 256;
    wconv_kernel<<<wconv_blocks, 256>>>(W2, W3, p_w2, p_w3);

    dim3 sgrid(HCDIM / BN, (N_NODES + BM - 1) / BM);
    int stats_blocks = (N_NODES * 32 + 255) / 256;   // warp per node

    // ---- layer 1 ----
    gemm_small_kernel<<<sgrid, 256>>>(x, W1, a1s, a1d, p_h, N_NODES, F_IN, HCDIM);
    stats_kernel<<<stats_blocks, 256>>>();
    aggregate_kernel<<<N_NODES, 128>>>(p_h, b1, p_xhi, p_xlo, nullptr, nullptr, nullptr, 0);

    // ---- layer 2 ----
    mma_gemm_kernel<<<NBLK, 256, GSMEM>>>(p_xhi, p_xlo, p_w2, a2s, a2d, p_h, N_NODES);
    stats_kernel<<<stats_blocks, 256>>>();
    aggregate_kernel<<<N_NODES, 128>>>(p_h, b2, p_xhi, p_xlo, nullptr, nullptr, nullptr, 0);

    // ---- layer 3 (aggregate + mean + bias + projection fused) ----
    mma_gemm_kernel<<<NBLK, 256, GSMEM>>>(p_xhi, p_xlo, p_w3, a3s, a3d, p_h, N_NODES);
    stats_kernel<<<stats_blocks, 256>>>();
    aggregate_kernel<<<N_NODES, 128>>>(p_h, b3, nullptr, nullptr, Wout, bout, out, 1);
}